// round 1
// baseline (speedup 1.0000x reference)
#include <cuda_runtime.h>

#define B_ 8
#define C_ 512
#define HW 1024
#define NH 8
#define DH 64
#define GROUPS 32
#define CPG 16           // C_/GROUPS
#define OC_QKV 1536

// -------- scratch (static device globals; no allocation) --------
__device__ float g_h[B_ * C_ * HW];        // normalized input  [B][C][HW]
__device__ float g_qkv[B_ * OC_QKV * HW];  // qkv               [B][3C][HW]
__device__ float g_att[B_ * C_ * HW];      // attention output  [B][C][HW]

// ============================ GroupNorm ============================
__global__ void groupnorm_kernel(const float* __restrict__ x,
                                 const float* __restrict__ gamma,
                                 const float* __restrict__ beta) {
    int bg = blockIdx.x;
    int b = bg >> 5, g = bg & 31;
    const int N = CPG * HW; // 16384
    size_t base = ((size_t)(b * C_ + g * CPG)) * HW;

    float s = 0.f, s2 = 0.f;
    for (int i = threadIdx.x; i < N; i += 256) {
        float v = x[base + i];
        s += v; s2 += v * v;
    }
    __shared__ float red[2][8];
    #pragma unroll
    for (int o = 16; o; o >>= 1) {
        s  += __shfl_xor_sync(~0u, s, o);
        s2 += __shfl_xor_sync(~0u, s2, o);
    }
    int w = threadIdx.x >> 5, l = threadIdx.x & 31;
    if (l == 0) { red[0][w] = s; red[1][w] = s2; }
    __syncthreads();
    if (threadIdx.x == 0) {
        float ts = 0.f, ts2 = 0.f;
        #pragma unroll
        for (int i = 0; i < 8; i++) { ts += red[0][i]; ts2 += red[1][i]; }
        float mu  = ts / N;
        float var = ts2 / N - mu * mu;
        red[0][0] = mu;
        red[1][0] = rsqrtf(var + 1e-5f);
    }
    __syncthreads();
    float mu = red[0][0], rstd = red[1][0];
    for (int i = threadIdx.x; i < N; i += 256) {
        int c = g * CPG + (i >> 10);
        float v = x[base + i];
        g_h[base + i] = (v - mu) * rstd * gamma[c] + beta[c];
    }
}

// ======================= 1x1-conv GEMM =======================
// out[b][o][p] = (res? x : 0) + bias[o] + sum_c w[o][c] * in[b][c][p]
// 64x64 output tile, BK=16, 256 threads, 4x4 per thread.
template <bool RES>
__global__ void gemm1x1_kernel(const float* __restrict__ in,
                               const float* __restrict__ w,
                               const float* __restrict__ bias,
                               const float* __restrict__ res,
                               float* __restrict__ out, int OC) {
    __shared__ __align__(16) float sA[16 * 65];  // sA[k][o] (W^T tile), pitch 65
    __shared__ __align__(16) float sB[16 * 64];  // sB[k][p]
    int b = blockIdx.z;
    int o0 = blockIdx.y * 64, p0 = blockIdx.x * 64;
    int tid = threadIdx.x, tx = tid & 15, ty = tid >> 4;

    float acc[4][4] = {};
    const float* wbase = w + (size_t)o0 * C_;
    const float* ibase = in + ((size_t)b * C_) * HW + p0;

    for (int c0 = 0; c0 < C_; c0 += 16) {
        __syncthreads();
        #pragma unroll
        for (int e = tid; e < 1024; e += 256) {
            int kk = e & 15, oo = e >> 4;
            sA[kk * 65 + oo] = wbase[(size_t)oo * C_ + c0 + kk];
            int kk2 = e >> 6, pp = e & 63;
            sB[kk2 * 64 + pp] = ibase[(size_t)(c0 + kk2) * HW + pp];
        }
        __syncthreads();
        #pragma unroll
        for (int kk = 0; kk < 16; kk++) {
            float a[4];
            #pragma unroll
            for (int r = 0; r < 4; r++) a[r] = sA[kk * 65 + ty * 4 + r];
            float4 bv = *(const float4*)&sB[kk * 64 + tx * 4];
            float bb[4] = {bv.x, bv.y, bv.z, bv.w};
            #pragma unroll
            for (int r = 0; r < 4; r++)
                #pragma unroll
                for (int c = 0; c < 4; c++)
                    acc[r][c] += a[r] * bb[c];
        }
    }

    #pragma unroll
    for (int r = 0; r < 4; r++) {
        int o = o0 + ty * 4 + r;
        float bb = bias[o];
        size_t oaddr = ((size_t)b * OC + o) * HW + p0 + tx * 4;
        float4 v;
        v.x = acc[r][0] + bb; v.y = acc[r][1] + bb;
        v.z = acc[r][2] + bb; v.w = acc[r][3] + bb;
        if (RES) {
            float4 rv = *(const float4*)&res[oaddr];
            v.x += rv.x; v.y += rv.y; v.z += rv.z; v.w += rv.w;
        }
        *(float4*)&out[oaddr] = v;
    }
}

// ======================= Attention (flash, no-max) =======================
// Per block: one (b, head), one 64-row query tile. Loop over 16 key tiles.
// Scores ~ N(0,1): exp() without max-subtraction is numerically safe here.
__global__ void attn_kernel() {
    extern __shared__ float sm[];
    float* sQ = sm;           // [64][64]  sQ[d][i]   (pre-scaled by DH^-0.5)
    float* sK = sm + 4096;    // [64][64]  sK[d][j]
    float* sV = sm + 8192;    // [64][65]  sV[j][d]   (pitch 65)
    float* sP = sm + 12352;   // [64][65]  sP[i][j]   (pitch 65)
    float* sR = sm + 16512;   // [16][65]  partial rowsums
    float* sL = sm + 17552;   // [64]      1/rowsum

    int bh = blockIdx.y;
    int b = bh >> 3, nh = bh & 7;
    int i0 = blockIdx.x * 64;
    int tid = threadIdx.x, tx = tid & 15, ty = tid >> 4;

    const float* qptr = g_qkv + ((size_t)(b * OC_QKV + nh * DH)) * HW + i0;
    const float* kptr = g_qkv + ((size_t)(b * OC_QKV + C_ + nh * DH)) * HW;
    const float* vptr = g_qkv + ((size_t)(b * OC_QKV + 2 * C_ + nh * DH)) * HW;

    for (int e = tid; e < 4096; e += 256) {
        int d = e >> 6, ii = e & 63;
        sQ[d * 64 + ii] = qptr[(size_t)d * HW + ii] * 0.125f;
    }

    float oacc[4][4] = {};
    float rowsum[4] = {};

    for (int j0 = 0; j0 < HW; j0 += 64) {
        __syncthreads();   // also covers Q load on first iter; prior PV done
        for (int e = tid; e < 4096; e += 256) {
            int d = e >> 6, jj = e & 63;
            float kv = kptr[(size_t)d * HW + j0 + jj];
            float vv = vptr[(size_t)d * HW + j0 + jj];
            sK[d * 64 + jj] = kv;
            sV[jj * 65 + d] = vv;       // transposed store, conflict-free (pitch 65)
        }
        __syncthreads();

        // S = Q^T K  (64x64 tile, 4x4 per thread)
        float s[4][4] = {};
        #pragma unroll 8
        for (int d = 0; d < 64; d++) {
            float4 aq = *(const float4*)&sQ[d * 64 + ty * 4];
            float4 ak = *(const float4*)&sK[d * 64 + tx * 4];
            float a[4] = {aq.x, aq.y, aq.z, aq.w};
            float k_[4] = {ak.x, ak.y, ak.z, ak.w};
            #pragma unroll
            for (int r = 0; r < 4; r++)
                #pragma unroll
                for (int c = 0; c < 4; c++)
                    s[r][c] += a[r] * k_[c];
        }

        // exp + accumulate row sums + stage P
        #pragma unroll
        for (int r = 0; r < 4; r++)
            #pragma unroll
            for (int c = 0; c < 4; c++) {
                float p = __expf(s[r][c]);
                rowsum[r] += p;
                sP[(ty * 4 + r) * 65 + tx * 4 + c] = p;
            }
        __syncthreads();

        // O += P V   (reduction over j; P reads broadcast, V 2-way conflict)
        #pragma unroll 8
        for (int j = 0; j < 64; j++) {
            float pa[4], vv[4];
            #pragma unroll
            for (int r = 0; r < 4; r++) pa[r] = sP[(ty * 4 + r) * 65 + j];
            #pragma unroll
            for (int c = 0; c < 4; c++) vv[c] = sV[j * 65 + tx * 4 + c];
            #pragma unroll
            for (int r = 0; r < 4; r++)
                #pragma unroll
                for (int c = 0; c < 4; c++)
                    oacc[r][c] += pa[r] * vv[c];
        }
    }

    // reduce rowsums across the 16 tx-threads sharing each row group
    #pragma unroll
    for (int r = 0; r < 4; r++) sR[tx * 65 + ty * 4 + r] = rowsum[r];
    __syncthreads();
    if (tid < 64) {
        float t = 0.f;
        #pragma unroll
        for (int u = 0; u < 16; u++) t += sR[u * 65 + tid];
        sL[tid] = 1.0f / t;
    }
    __syncthreads();

    // write O with the torch-faithful "direct reshape" channel mapping:
    // (b, nh, i, d) -> channel c = nh*64 + (i>>4), pos p = (i&15)*64 + d
    #pragma unroll
    for (int r = 0; r < 4; r++) {
        int il = ty * 4 + r;
        float inv = sL[il];
        int i = i0 + il;
        int c_out = nh * 64 + (i >> 4);
        int p = (i & 15) * 64 + tx * 4;
        size_t addr = ((size_t)(b * C_ + c_out)) * HW + p;
        float4 v = {oacc[r][0] * inv, oacc[r][1] * inv,
                    oacc[r][2] * inv, oacc[r][3] * inv};
        *(float4*)&g_att[addr] = v;
    }
}

// ============================ launch ============================
extern "C" void kernel_launch(void* const* d_in, const int* in_sizes, int n_in,
                              void* d_out, int out_size) {
    const float* x      = (const float*)d_in[0];
    const float* gamma  = (const float*)d_in[1];
    const float* beta   = (const float*)d_in[2];
    const float* qkv_w  = (const float*)d_in[3];
    const float* qkv_b  = (const float*)d_in[4];
    const float* proj_w = (const float*)d_in[5];
    const float* proj_b = (const float*)d_in[6];
    float* out = (float*)d_out;

    void *p_h = nullptr, *p_qkv = nullptr, *p_att = nullptr;
    cudaGetSymbolAddress(&p_h, g_h);
    cudaGetSymbolAddress(&p_qkv, g_qkv);
    cudaGetSymbolAddress(&p_att, g_att);

    const int ATTN_SMEM = 17616 * 4;  // 70464 bytes
    cudaFuncSetAttribute(attn_kernel,
                         cudaFuncAttributeMaxDynamicSharedMemorySize, ATTN_SMEM);

    // 1. GroupNorm
    groupnorm_kernel<<<B_ * GROUPS, 256>>>(x, gamma, beta);

    // 2. QKV = W_qkv @ h + b_qkv     [B][1536][HW]
    gemm1x1_kernel<false><<<dim3(16, 24, B_), 256>>>(
        (const float*)p_h, qkv_w, qkv_b, nullptr, (float*)p_qkv, OC_QKV);

    // 3. Attention
    attn_kernel<<<dim3(16, B_ * NH), 256, ATTN_SMEM>>>();

    // 4. out = x + W_proj @ att + b_proj
    gemm1x1_kernel<true><<<dim3(16, 8, B_), 256>>>(
        (const float*)p_att, proj_w, proj_b, x, out, C_);
}

// round 2
// speedup vs baseline: 1.2728x; 1.2728x over previous
#include <cuda_runtime.h>
#include <mma.h>
using namespace nvcuda;

#define B_ 8
#define C_ 512
#define HW 1024
#define NH 8
#define DH 64
#define GROUPS 32
#define CPG 16
#define OC_QKV 1536

// -------- scratch (static device globals; no allocation) --------
__device__ float g_h[B_ * C_ * HW];        // normalized input  [B][C][HW]
__device__ float g_qkv[B_ * OC_QKV * HW];  // qkv               [B][3C][HW]
__device__ float g_att[B_ * C_ * HW];      // attention output  [B][C][HW]

// ============================ GroupNorm ============================
__global__ void groupnorm_kernel(const float* __restrict__ x,
                                 const float* __restrict__ gamma,
                                 const float* __restrict__ beta) {
    int bg = blockIdx.x;
    int b = bg >> 5, g = bg & 31;
    const int N = CPG * HW;
    size_t base = ((size_t)(b * C_ + g * CPG)) * HW;

    float s = 0.f, s2 = 0.f;
    for (int i = threadIdx.x; i < N; i += 256) {
        float v = x[base + i];
        s += v; s2 += v * v;
    }
    __shared__ float red[2][8];
    #pragma unroll
    for (int o = 16; o; o >>= 1) {
        s  += __shfl_xor_sync(~0u, s, o);
        s2 += __shfl_xor_sync(~0u, s2, o);
    }
    int w = threadIdx.x >> 5, l = threadIdx.x & 31;
    if (l == 0) { red[0][w] = s; red[1][w] = s2; }
    __syncthreads();
    if (threadIdx.x == 0) {
        float ts = 0.f, ts2 = 0.f;
        #pragma unroll
        for (int i = 0; i < 8; i++) { ts += red[0][i]; ts2 += red[1][i]; }
        float mu  = ts / N;
        float var = ts2 / N - mu * mu;
        red[0][0] = mu;
        red[1][0] = rsqrtf(var + 1e-5f);
    }
    __syncthreads();
    float mu = red[0][0], rstd = red[1][0];
    for (int i = threadIdx.x; i < N; i += 256) {
        int c = g * CPG + (i >> 10);
        float v = x[base + i];
        g_h[base + i] = (v - mu) * rstd * gamma[c] + beta[c];
    }
}

// ======================= TF32 wmma 1x1-conv GEMM =======================
// out[b][o][p] = (res? x : 0) + bias[o] + sum_c w[o][c] * in[b][c][p]
// Block tile: 128(o) x 64(p), BK=16, 256 threads = 8 warps, 2x2 wmma frags each.
template <bool RES>
__global__ void gemm_wmma(const float* __restrict__ in,
                          const float* __restrict__ w,
                          const float* __restrict__ bias,
                          const float* __restrict__ res,
                          float* __restrict__ out, int OC) {
    extern __shared__ float smem[];
    float* sA = smem;           // [128][20]  A[m][k], pitch 20
    float* sB = smem + 2560;    // [16][68]   B[k][n], pitch 68
    float* sC = smem;           // [128][68]  epilogue reuse

    int b = blockIdx.z;
    int o0 = blockIdx.y * 128, p0 = blockIdx.x * 64;
    int tid = threadIdx.x;
    int wid = tid >> 5;
    int wm = wid >> 1, wn = wid & 1;

    wmma::fragment<wmma::accumulator, 16, 16, 8, float> acc[2][2];
    #pragma unroll
    for (int i = 0; i < 2; i++)
        #pragma unroll
        for (int j = 0; j < 2; j++) wmma::fill_fragment(acc[i][j], 0.0f);

    const float* wbase = w + (size_t)o0 * C_;
    const float* ibase = in + ((size_t)b * C_) * HW + p0;

    for (int c0 = 0; c0 < C_; c0 += 16) {
        __syncthreads();
        // A: 128x16 = 512 float4, 2 per thread
        #pragma unroll
        for (int u = 0; u < 2; u++) {
            int idx = tid + u * 256;
            int o = idx >> 2, kq = (idx & 3) * 4;
            float4 v = *(const float4*)&wbase[(size_t)o * C_ + c0 + kq];
            *(float4*)&sA[o * 20 + kq] = v;
        }
        // B: 16x64 = 256 float4, 1 per thread
        {
            int k = tid >> 4, pq = (tid & 15) * 4;
            float4 v = *(const float4*)&ibase[(size_t)(c0 + k) * HW + pq];
            *(float4*)&sB[k * 68 + pq] = v;
        }
        __syncthreads();

        #pragma unroll
        for (int kk = 0; kk < 16; kk += 8) {
            wmma::fragment<wmma::matrix_a, 16, 16, 8, wmma::precision::tf32, wmma::row_major> af[2];
            wmma::fragment<wmma::matrix_b, 16, 16, 8, wmma::precision::tf32, wmma::row_major> bf[2];
            #pragma unroll
            for (int mi = 0; mi < 2; mi++) {
                wmma::load_matrix_sync(af[mi], &sA[(wm * 32 + mi * 16) * 20 + kk], 20);
                #pragma unroll
                for (int t = 0; t < af[mi].num_elements; t++)
                    af[mi].x[t] = wmma::__float_to_tf32(af[mi].x[t]);
            }
            #pragma unroll
            for (int ni = 0; ni < 2; ni++) {
                wmma::load_matrix_sync(bf[ni], &sB[kk * 68 + wn * 32 + ni * 16], 68);
                #pragma unroll
                for (int t = 0; t < bf[ni].num_elements; t++)
                    bf[ni].x[t] = wmma::__float_to_tf32(bf[ni].x[t]);
            }
            #pragma unroll
            for (int mi = 0; mi < 2; mi++)
                #pragma unroll
                for (int ni = 0; ni < 2; ni++)
                    wmma::mma_sync(acc[mi][ni], af[mi], bf[ni], acc[mi][ni]);
        }
    }

    __syncthreads();
    #pragma unroll
    for (int mi = 0; mi < 2; mi++)
        #pragma unroll
        for (int ni = 0; ni < 2; ni++)
            wmma::store_matrix_sync(&sC[(wm * 32 + mi * 16) * 68 + wn * 32 + ni * 16],
                                    acc[mi][ni], 68, wmma::mem_row_major);
    __syncthreads();

    // write: 128x64 = 2048 float4, 8 per thread
    #pragma unroll
    for (int u = 0; u < 8; u++) {
        int idx = tid + u * 256;
        int o = idx >> 4, pq = (idx & 15) * 4;
        float4 v = *(float4*)&sC[o * 68 + pq];
        float bb = bias[o0 + o];
        size_t oaddr = ((size_t)b * OC + o0 + o) * HW + p0 + pq;
        v.x += bb; v.y += bb; v.z += bb; v.w += bb;
        if (RES) {
            float4 rv = *(const float4*)&res[oaddr];
            v.x += rv.x; v.y += rv.y; v.z += rv.z; v.w += rv.w;
        }
        *(float4*)&out[oaddr] = v;
    }
}

// ======================= TF32 wmma attention =======================
// Block: one (b,head), 64-row query tile, 256 threads = 8 warps.
// S = Q K^T via wmma (K tile used untransposed: [d][j] is row-major B).
// O = P V   via wmma (V tile [d][j] is col-major B). No max subtraction.
__global__ void attn_wmma() {
    extern __shared__ float smem[];
    float* sQ = smem;            // [64][68]  Q[i][d]
    float* sK = smem + 4352;     // [64][68]  K[d][j]
    float* sV = smem + 8704;     // [64][68]  V[d][j]
    float* sS = smem + 13056;    // [64][68]  S/P/O staging [i][*]
    float* sL = smem + 17408;    // [64]      1/rowsum

    int bh = blockIdx.y;
    int b = bh >> 3, nh = bh & 7;
    int i0 = blockIdx.x * 64;
    int tid = threadIdx.x;
    int wid = tid >> 5;
    int wr = wid >> 1;            // row strip 0..3 (16 rows)
    int wc = (wid & 1) * 32;      // col strip base

    const float* qptr = g_qkv + ((size_t)(b * OC_QKV + nh * DH)) * HW + i0;
    const float* kptr = g_qkv + ((size_t)(b * OC_QKV + C_ + nh * DH)) * HW;
    const float* vptr = g_qkv + ((size_t)(b * OC_QKV + 2 * C_ + nh * DH)) * HW;

    // load Q transposed (i-major), pre-scaled
    #pragma unroll
    for (int e = tid; e < 4096; e += 256) {
        int d = e >> 6, i = e & 63;
        sQ[i * 68 + d] = qptr[(size_t)d * HW + i] * 0.125f;
    }

    wmma::fragment<wmma::accumulator, 16, 16, 8, float> acc_o[2];
    #pragma unroll
    for (int ci = 0; ci < 2; ci++) wmma::fill_fragment(acc_o[ci], 0.0f);
    float rsum = 0.f;
    int row = tid >> 2, q4 = (tid & 3) * 16;

    for (int j0 = 0; j0 < HW; j0 += 64) {
        __syncthreads();   // covers Q load (iter 0) / prior PV reads of sK,sV,sS
        // load K,V tiles (no transpose): 1024 float4 each
        #pragma unroll
        for (int u = 0; u < 4; u++) {
            int idx = tid + u * 256;
            int d = idx >> 4, jq = (idx & 15) * 4;
            *(float4*)&sK[d * 68 + jq] = *(const float4*)&kptr[(size_t)d * HW + j0 + jq];
            *(float4*)&sV[d * 68 + jq] = *(const float4*)&vptr[(size_t)d * HW + j0 + jq];
        }
        __syncthreads();

        // S = Q K^T
        wmma::fragment<wmma::accumulator, 16, 16, 8, float> acc_s[2];
        #pragma unroll
        for (int ci = 0; ci < 2; ci++) wmma::fill_fragment(acc_s[ci], 0.0f);
        #pragma unroll
        for (int kk = 0; kk < 64; kk += 8) {
            wmma::fragment<wmma::matrix_a, 16, 16, 8, wmma::precision::tf32, wmma::row_major> af;
            wmma::load_matrix_sync(af, &sQ[(wr * 16) * 68 + kk], 68);
            #pragma unroll
            for (int t = 0; t < af.num_elements; t++) af.x[t] = wmma::__float_to_tf32(af.x[t]);
            #pragma unroll
            for (int ci = 0; ci < 2; ci++) {
                wmma::fragment<wmma::matrix_b, 16, 16, 8, wmma::precision::tf32, wmma::row_major> bf;
                wmma::load_matrix_sync(bf, &sK[kk * 68 + wc + ci * 16], 68);
                #pragma unroll
                for (int t = 0; t < bf.num_elements; t++) bf.x[t] = wmma::__float_to_tf32(bf.x[t]);
                wmma::mma_sync(acc_s[ci], af, bf, acc_s[ci]);
            }
        }
        #pragma unroll
        for (int ci = 0; ci < 2; ci++)
            wmma::store_matrix_sync(&sS[(wr * 16) * 68 + wc + ci * 16], acc_s[ci], 68,
                                    wmma::mem_row_major);
        __syncthreads();

        // exp + rowsum (thread covers 16 j's of one row)
        #pragma unroll
        for (int z = 0; z < 16; z++) {
            int idx = row * 68 + q4 + z;
            float p = __expf(sS[idx]);
            sS[idx] = p;
            rsum += p;
        }
        __syncthreads();

        // O += P V
        #pragma unroll
        for (int kk = 0; kk < 64; kk += 8) {
            wmma::fragment<wmma::matrix_a, 16, 16, 8, wmma::precision::tf32, wmma::row_major> af;
            wmma::load_matrix_sync(af, &sS[(wr * 16) * 68 + kk], 68);
            #pragma unroll
            for (int t = 0; t < af.num_elements; t++) af.x[t] = wmma::__float_to_tf32(af.x[t]);
            #pragma unroll
            for (int ci = 0; ci < 2; ci++) {
                wmma::fragment<wmma::matrix_b, 16, 16, 8, wmma::precision::tf32, wmma::col_major> bf;
                wmma::load_matrix_sync(bf, &sV[(wc + ci * 16) * 68 + kk], 68);
                #pragma unroll
                for (int t = 0; t < bf.num_elements; t++) bf.x[t] = wmma::__float_to_tf32(bf.x[t]);
                wmma::mma_sync(acc_o[ci], af, bf, acc_o[ci]);
            }
        }
    }

    // rowsum across the 4 lanes sharing each row
    rsum += __shfl_xor_sync(~0u, rsum, 1);
    rsum += __shfl_xor_sync(~0u, rsum, 2);
    if ((tid & 3) == 0) sL[row] = 1.0f / rsum;
    __syncthreads();

    #pragma unroll
    for (int ci = 0; ci < 2; ci++)
        wmma::store_matrix_sync(&sS[(wr * 16) * 68 + wc + ci * 16], acc_o[ci], 68,
                                wmma::mem_row_major);
    __syncthreads();

    // write with torch-faithful reshape: (b,nh,i,d)->c=nh*64+(i>>4), p=(i&15)*64+d
    {
        int il = tid >> 2, dq = (tid & 3) * 16;
        float inv = sL[il];
        int i = i0 + il;
        int c_out = nh * 64 + (i >> 4);
        int p = (i & 15) * 64 + dq;
        size_t base = ((size_t)(b * C_ + c_out)) * HW + p;
        #pragma unroll
        for (int z = 0; z < 4; z++) {
            float4 v = *(float4*)&sS[il * 68 + dq + z * 4];
            v.x *= inv; v.y *= inv; v.z *= inv; v.w *= inv;
            *(float4*)&g_att[base + z * 4] = v;
        }
    }
}

// ============================ launch ============================
extern "C" void kernel_launch(void* const* d_in, const int* in_sizes, int n_in,
                              void* d_out, int out_size) {
    const float* x      = (const float*)d_in[0];
    const float* gamma  = (const float*)d_in[1];
    const float* beta   = (const float*)d_in[2];
    const float* qkv_w  = (const float*)d_in[3];
    const float* qkv_b  = (const float*)d_in[4];
    const float* proj_w = (const float*)d_in[5];
    const float* proj_b = (const float*)d_in[6];
    float* out = (float*)d_out;

    void *p_h = nullptr, *p_qkv = nullptr, *p_att = nullptr;
    cudaGetSymbolAddress(&p_h, g_h);
    cudaGetSymbolAddress(&p_qkv, g_qkv);
    cudaGetSymbolAddress(&p_att, g_att);

    const int GEMM_SMEM = 8704 * 4;          // 34816 B
    const int ATTN_SMEM = (17408 + 64) * 4;  // 69888 B
    static bool attr_done = false;
    if (!attr_done) {
        cudaFuncSetAttribute(attn_wmma,
                             cudaFuncAttributeMaxDynamicSharedMemorySize, ATTN_SMEM);
        cudaFuncSetAttribute(gemm_wmma<false>,
                             cudaFuncAttributeMaxDynamicSharedMemorySize, GEMM_SMEM);
        cudaFuncSetAttribute(gemm_wmma<true>,
                             cudaFuncAttributeMaxDynamicSharedMemorySize, GEMM_SMEM);
        attr_done = true;
    }

    // 1. GroupNorm
    groupnorm_kernel<<<B_ * GROUPS, 256>>>(x, gamma, beta);

    // 2. QKV
    gemm_wmma<false><<<dim3(16, 12, B_), 256, GEMM_SMEM>>>(
        (const float*)p_h, qkv_w, qkv_b, nullptr, (float*)p_qkv, OC_QKV);

    // 3. Attention
    attn_wmma<<<dim3(16, B_ * NH), 256, ATTN_SMEM>>>();

    // 4. out = x + proj(att)
    gemm_wmma<true><<<dim3(16, 4, B_), 256, GEMM_SMEM>>>(
        (const float*)p_att, proj_w, proj_b, x, out, C_);
}

// round 3
// speedup vs baseline: 3.1439x; 2.4702x over previous
#include <cuda_runtime.h>
#include <cuda_bf16.h>
#include <mma.h>
using namespace nvcuda;

#define B_ 8
#define C_ 512
#define HW 1024
#define NH 8
#define DH 64
#define GROUPS 32
#define CPG 16
#define OC_QKV 1536

typedef __nv_bfloat16 bf16;

// -------- scratch (static device globals; no allocation) --------
__device__ bf16 g_h[B_ * C_ * HW];         // normalized input  [B][C][HW]
__device__ bf16 g_qkv[B_ * OC_QKV * HW];   // qkv               [B][3C][HW]
__device__ bf16 g_att[B_ * C_ * HW];       // attention output  [B][C][HW]

// ============================ GroupNorm ============================
__global__ void groupnorm_kernel(const float* __restrict__ x,
                                 const float* __restrict__ gamma,
                                 const float* __restrict__ beta) {
    int bg = blockIdx.x;
    int b = bg >> 5, g = bg & 31;
    const int N = CPG * HW;
    size_t base = ((size_t)(b * C_ + g * CPG)) * HW;

    float s = 0.f, s2 = 0.f;
    for (int i = threadIdx.x; i < N; i += 256) {
        float v = x[base + i];
        s += v; s2 += v * v;
    }
    __shared__ float red[2][8];
    #pragma unroll
    for (int o = 16; o; o >>= 1) {
        s  += __shfl_xor_sync(~0u, s, o);
        s2 += __shfl_xor_sync(~0u, s2, o);
    }
    int w = threadIdx.x >> 5, l = threadIdx.x & 31;
    if (l == 0) { red[0][w] = s; red[1][w] = s2; }
    __syncthreads();
    if (threadIdx.x == 0) {
        float ts = 0.f, ts2 = 0.f;
        #pragma unroll
        for (int i = 0; i < 8; i++) { ts += red[0][i]; ts2 += red[1][i]; }
        float mu  = ts / N;
        float var = ts2 / N - mu * mu;
        red[0][0] = mu;
        red[1][0] = rsqrtf(var + 1e-5f);
    }
    __syncthreads();
    float mu = red[0][0], rstd = red[1][0];
    for (int i = threadIdx.x; i < N; i += 256) {
        int c = g * CPG + (i >> 10);
        float v = x[base + i];
        g_h[base + i] = __float2bfloat16((v - mu) * rstd * gamma[c] + beta[c]);
    }
}

// ======================= BF16 wmma 1x1-conv GEMM =======================
// out[b][o][p] = (res? x : 0) + bias[o] + sum_c w[o][c] * in[b][c][p]
// Block tile: 128(o) x 64(p), BK=32, 256 threads = 8 warps, 2x2 frags each.
// RES=false: out is bf16 (g_qkv). RES=true: out is fp32 (+residual).
template <bool RES>
__global__ void gemm_wmma(const bf16* __restrict__ in,
                          const float* __restrict__ w,
                          const float* __restrict__ bias,
                          const float* __restrict__ res,
                          void* __restrict__ outv, int OC) {
    extern __shared__ char smc[];
    bf16*  sA = (bf16*)smc;             // [128][40] bf16, pitch 40
    bf16*  sB = (bf16*)(smc + 10240);   // [32][72]  bf16, pitch 72
    float* sC = (float*)smc;            // [128][68] fp32 epilogue overlay

    int b = blockIdx.z;
    int o0 = blockIdx.y * 128, p0 = blockIdx.x * 64;
    int tid = threadIdx.x;
    int wid = tid >> 5;
    int wm = wid >> 1, wn = wid & 1;

    wmma::fragment<wmma::accumulator, 16, 16, 16, float> acc[2][2];
    #pragma unroll
    for (int i = 0; i < 2; i++)
        #pragma unroll
        for (int j = 0; j < 2; j++) wmma::fill_fragment(acc[i][j], 0.0f);

    const float* wbase = w + (size_t)o0 * C_;
    const bf16*  ibase = in + ((size_t)b * C_) * HW + p0;

    for (int c0 = 0; c0 < C_; c0 += 32) {
        __syncthreads();
        // A: 128x32 fp32 -> bf16; 1024 float4, 4 per thread
        #pragma unroll
        for (int u = 0; u < 4; u++) {
            int idx = tid + u * 256;
            int o = idx >> 3, kq = (idx & 7) * 4;
            float4 v = *(const float4*)&wbase[(size_t)o * C_ + c0 + kq];
            __nv_bfloat162 lo = __floats2bfloat162_rn(v.x, v.y);
            __nv_bfloat162 hi = __floats2bfloat162_rn(v.z, v.w);
            uint2 pk = {*(unsigned*)&lo, *(unsigned*)&hi};
            *(uint2*)&sA[o * 40 + kq] = pk;
        }
        // B: 32x64 bf16 copy; 256 uint4 (8 bf16 each), 1 per thread
        {
            int k = tid >> 3, jq = (tid & 7) * 8;
            *(uint4*)&sB[k * 72 + jq] =
                *(const uint4*)&ibase[(size_t)(c0 + k) * HW + jq];
        }
        __syncthreads();

        #pragma unroll
        for (int kk = 0; kk < 32; kk += 16) {
            wmma::fragment<wmma::matrix_a, 16, 16, 16, bf16, wmma::row_major> af[2];
            wmma::fragment<wmma::matrix_b, 16, 16, 16, bf16, wmma::row_major> bfr[2];
            #pragma unroll
            for (int mi = 0; mi < 2; mi++)
                wmma::load_matrix_sync(af[mi], &sA[(wm * 32 + mi * 16) * 40 + kk], 40);
            #pragma unroll
            for (int ni = 0; ni < 2; ni++)
                wmma::load_matrix_sync(bfr[ni], &sB[kk * 72 + wn * 32 + ni * 16], 72);
            #pragma unroll
            for (int mi = 0; mi < 2; mi++)
                #pragma unroll
                for (int ni = 0; ni < 2; ni++)
                    wmma::mma_sync(acc[mi][ni], af[mi], bfr[ni], acc[mi][ni]);
        }
    }

    __syncthreads();
    #pragma unroll
    for (int mi = 0; mi < 2; mi++)
        #pragma unroll
        for (int ni = 0; ni < 2; ni++)
            wmma::store_matrix_sync(&sC[(wm * 32 + mi * 16) * 68 + wn * 32 + ni * 16],
                                    acc[mi][ni], 68, wmma::mem_row_major);
    __syncthreads();

    // write: 128x64, 8 float4-equivalents per thread
    #pragma unroll
    for (int u = 0; u < 8; u++) {
        int idx = tid + u * 256;
        int o = idx >> 4, pq = (idx & 15) * 4;
        float4 v = *(float4*)&sC[o * 68 + pq];
        float bb = bias[o0 + o];
        size_t oaddr = ((size_t)b * OC + o0 + o) * HW + p0 + pq;
        v.x += bb; v.y += bb; v.z += bb; v.w += bb;
        if (RES) {
            float4 rv = *(const float4*)&res[oaddr];
            v.x += rv.x; v.y += rv.y; v.z += rv.z; v.w += rv.w;
            *(float4*)&((float*)outv)[oaddr] = v;
        } else {
            __nv_bfloat162 lo = __floats2bfloat162_rn(v.x, v.y);
            __nv_bfloat162 hi = __floats2bfloat162_rn(v.z, v.w);
            uint2 pk = {*(unsigned*)&lo, *(unsigned*)&hi};
            *(uint2*)&((bf16*)outv)[oaddr] = pk;
        }
    }
}

// ======================= BF16 wmma attention =======================
// Block: one (b,head), 64-row query tile, 256 threads = 8 warps.
// S = Q K^T (K tile [d][j] used as row-major B);
// O = P V   (V tile [d][j] used as col-major B). No max subtraction.
__global__ void attn_wmma() {
    extern __shared__ char smc[];
    bf16*  sQ = (bf16*)smc;             // [64][72]  Q[i][d]
    bf16*  sK = (bf16*)(smc + 9216);    // [64][72]  K[d][j]
    bf16*  sV = (bf16*)(smc + 18432);   // [64][72]  V[d][j]
    bf16*  sP = (bf16*)(smc + 27648);   // [64][72]  P[i][j] bf16
    float* sS = (float*)(smc + 36864);  // [64][68]  S / O staging fp32
    float* sL = (float*)(smc + 54272);  // [64]      1/rowsum

    int bh = blockIdx.y;
    int b = bh >> 3, nh = bh & 7;
    int i0 = blockIdx.x * 64;
    int tid = threadIdx.x;
    int wid = tid >> 5;
    int wr = wid >> 1;            // row strip 0..3 (16 rows)
    int wc = (wid & 1) * 32;      // col strip base

    const bf16* qptr = g_qkv + ((size_t)(b * OC_QKV + nh * DH)) * HW + i0;
    const bf16* kptr = g_qkv + ((size_t)(b * OC_QKV + C_ + nh * DH)) * HW;
    const bf16* vptr = g_qkv + ((size_t)(b * OC_QKV + 2 * C_ + nh * DH)) * HW;

    // load Q transposed (i-major), pre-scaled by DH^-0.5 = 0.125 (exact pow2)
    #pragma unroll
    for (int e = tid; e < 4096; e += 256) {
        int d = e >> 6, i = e & 63;
        float q = __bfloat162float(qptr[(size_t)d * HW + i]) * 0.125f;
        sQ[i * 72 + d] = __float2bfloat16(q);
    }

    wmma::fragment<wmma::accumulator, 16, 16, 16, float> acc_o[2];
    #pragma unroll
    for (int ci = 0; ci < 2; ci++) wmma::fill_fragment(acc_o[ci], 0.0f);
    float rsum = 0.f;
    int row = tid >> 2, q4 = (tid & 3) * 16;

    for (int j0 = 0; j0 < HW; j0 += 64) {
        __syncthreads();   // covers Q load (iter 0) / prior PV reads
        // load K,V tiles: 64x64 bf16 each = 512 uint4 each; 2+2 per thread
        #pragma unroll
        for (int u = 0; u < 2; u++) {
            int idx = tid + u * 256;
            int d = idx >> 3, jq = (idx & 7) * 8;
            *(uint4*)&sK[d * 72 + jq] =
                *(const uint4*)&kptr[(size_t)d * HW + j0 + jq];
            *(uint4*)&sV[d * 72 + jq] =
                *(const uint4*)&vptr[(size_t)d * HW + j0 + jq];
        }
        __syncthreads();

        // S = Q K^T
        wmma::fragment<wmma::accumulator, 16, 16, 16, float> acc_s[2];
        #pragma unroll
        for (int ci = 0; ci < 2; ci++) wmma::fill_fragment(acc_s[ci], 0.0f);
        #pragma unroll
        for (int kk = 0; kk < 64; kk += 16) {
            wmma::fragment<wmma::matrix_a, 16, 16, 16, bf16, wmma::row_major> af;
            wmma::load_matrix_sync(af, &sQ[(wr * 16) * 72 + kk], 72);
            #pragma unroll
            for (int ci = 0; ci < 2; ci++) {
                wmma::fragment<wmma::matrix_b, 16, 16, 16, bf16, wmma::row_major> bfr;
                wmma::load_matrix_sync(bfr, &sK[kk * 72 + wc + ci * 16], 72);
                wmma::mma_sync(acc_s[ci], af, bfr, acc_s[ci]);
            }
        }
        #pragma unroll
        for (int ci = 0; ci < 2; ci++)
            wmma::store_matrix_sync(&sS[(wr * 16) * 68 + wc + ci * 16], acc_s[ci], 68,
                                    wmma::mem_row_major);
        __syncthreads();

        // exp + rowsum; stage P as bf16
        #pragma unroll
        for (int z = 0; z < 16; z++) {
            float p = __expf(sS[row * 68 + q4 + z]);
            rsum += p;
            sP[row * 72 + q4 + z] = __float2bfloat16(p);
        }
        __syncthreads();

        // O += P V
        #pragma unroll
        for (int kk = 0; kk < 64; kk += 16) {
            wmma::fragment<wmma::matrix_a, 16, 16, 16, bf16, wmma::row_major> af;
            wmma::load_matrix_sync(af, &sP[(wr * 16) * 72 + kk], 72);
            #pragma unroll
            for (int ci = 0; ci < 2; ci++) {
                wmma::fragment<wmma::matrix_b, 16, 16, 16, bf16, wmma::col_major> bfr;
                wmma::load_matrix_sync(bfr, &sV[(wc + ci * 16) * 72 + kk], 72);
                wmma::mma_sync(acc_o[ci], af, bfr, acc_o[ci]);
            }
        }
    }

    // rowsum across the 4 lanes sharing each row
    rsum += __shfl_xor_sync(~0u, rsum, 1);
    rsum += __shfl_xor_sync(~0u, rsum, 2);
    if ((tid & 3) == 0) sL[row] = 1.0f / rsum;
    __syncthreads();

    #pragma unroll
    for (int ci = 0; ci < 2; ci++)
        wmma::store_matrix_sync(&sS[(wr * 16) * 68 + wc + ci * 16], acc_o[ci], 68,
                                wmma::mem_row_major);
    __syncthreads();

    // write bf16 with torch-faithful reshape:
    // (b,nh,i,d) -> c = nh*64 + (i>>4), p = (i&15)*64 + d
    {
        int il = tid >> 2, dq = (tid & 3) * 16;
        float inv = sL[il];
        int i = i0 + il;
        int c_out = nh * 64 + (i >> 4);
        int p = (i & 15) * 64 + dq;
        size_t base = ((size_t)(b * C_ + c_out)) * HW + p;
        #pragma unroll
        for (int z = 0; z < 4; z++) {
            float4 v = *(float4*)&sS[il * 68 + dq + z * 4];
            __nv_bfloat162 lo = __floats2bfloat162_rn(v.x * inv, v.y * inv);
            __nv_bfloat162 hi = __floats2bfloat162_rn(v.z * inv, v.w * inv);
            uint2 pk = {*(unsigned*)&lo, *(unsigned*)&hi};
            *(uint2*)&g_att[base + z * 4] = pk;
        }
    }
}

// ============================ launch ============================
extern "C" void kernel_launch(void* const* d_in, const int* in_sizes, int n_in,
                              void* d_out, int out_size) {
    const float* x      = (const float*)d_in[0];
    const float* gamma  = (const float*)d_in[1];
    const float* beta   = (const float*)d_in[2];
    const float* qkv_w  = (const float*)d_in[3];
    const float* qkv_b  = (const float*)d_in[4];
    const float* proj_w = (const float*)d_in[5];
    const float* proj_b = (const float*)d_in[6];
    float* out = (float*)d_out;

    void *p_h = nullptr, *p_qkv = nullptr, *p_att = nullptr;
    cudaGetSymbolAddress(&p_h, g_h);
    cudaGetSymbolAddress(&p_qkv, g_qkv);
    cudaGetSymbolAddress(&p_att, g_att);

    const int GEMM_SMEM = 34816;   // max(tiles 14848, epilogue 128*68*4)
    const int ATTN_SMEM = 54528;
    cudaFuncSetAttribute(attn_wmma,
                         cudaFuncAttributeMaxDynamicSharedMemorySize, ATTN_SMEM);

    // 1. GroupNorm -> bf16 h
    groupnorm_kernel<<<B_ * GROUPS, 256>>>(x, gamma, beta);

    // 2. QKV (bf16 in, bf16 out)
    gemm_wmma<false><<<dim3(16, 12, B_), 256, GEMM_SMEM>>>(
        (const bf16*)p_h, qkv_w, qkv_b, nullptr, p_qkv, OC_QKV);

    // 3. Attention (bf16 in/out)
    attn_wmma<<<dim3(16, B_ * NH), 256, ATTN_SMEM>>>();

    // 4. out = x + proj(att)  (fp32 out)
    gemm_wmma<true><<<dim3(16, 4, B_), 256, GEMM_SMEM>>>(
        (const bf16*)p_att, proj_w, proj_b, x, out, C_);
}

// round 4
// speedup vs baseline: 3.4310x; 1.0913x over previous
#include <cuda_runtime.h>
#include <cuda_bf16.h>
#include <mma.h>
using namespace nvcuda;

#define B_ 8
#define C_ 512
#define HW 1024
#define NH 8
#define DH 64
#define OC_QKV 1536

typedef __nv_bfloat16 bf16;

// -------- scratch (static device globals; no allocation) --------
__device__ bf16 g_h[B_ * C_ * HW];
__device__ bf16 g_qkv[B_ * OC_QKV * HW];
__device__ bf16 g_att[B_ * C_ * HW];
__device__ bf16 g_wq[OC_QKV * C_];
__device__ bf16 g_wp[C_ * C_];

// -------- helpers --------
__device__ __forceinline__ void cp16(void* dst, const void* src) {
    unsigned d = (unsigned)__cvta_generic_to_shared(dst);
    asm volatile("cp.async.cg.shared.global [%0], [%1], 16;\n" :: "r"(d), "l"(src));
}
__device__ __forceinline__ void cp_commit() { asm volatile("cp.async.commit_group;\n" ::); }
__device__ __forceinline__ void cp_wait0()  { asm volatile("cp.async.wait_group 0;\n" ::); }

__device__ __forceinline__ uint2 pack4(float a, float b, float c, float d) {
    __nv_bfloat162 lo = __floats2bfloat162_rn(a, b);
    __nv_bfloat162 hi = __floats2bfloat162_rn(c, d);
    uint2 r; r.x = *(unsigned*)&lo; r.y = *(unsigned*)&hi; return r;
}

// ============== weight fp32 -> bf16 (run once per graph) ==============
__global__ void wconv(const float* __restrict__ s, bf16* __restrict__ d, int n4) {
    int i = blockIdx.x * 256 + threadIdx.x;
    if (i < n4) {
        float4 v = ((const float4*)s)[i];
        ((uint2*)d)[i] = pack4(v.x, v.y, v.z, v.w);
    }
}

// ============================ GroupNorm ============================
// one block per (b, group); group data (64 KB) cached in smem -> single read.
__global__ void groupnorm_kernel(const float* __restrict__ x,
                                 const float* __restrict__ gamma,
                                 const float* __restrict__ beta) {
    extern __shared__ float4 sx[];   // 4096 float4 = 16384 floats
    int bg = blockIdx.x;
    int b = bg >> 5, g = bg & 31;
    size_t base = ((size_t)(b * C_ + g * 16)) * HW;
    const float4* xin = (const float4*)(x + base);

    float s = 0.f, s2 = 0.f;
    for (int q = threadIdx.x; q < 4096; q += 256) {
        float4 v = xin[q];
        sx[q] = v;
        s  += v.x + v.y + v.z + v.w;
        s2 += v.x * v.x + v.y * v.y + v.z * v.z + v.w * v.w;
    }
    __shared__ float red[2][8];
    #pragma unroll
    for (int o = 16; o; o >>= 1) {
        s  += __shfl_xor_sync(~0u, s, o);
        s2 += __shfl_xor_sync(~0u, s2, o);
    }
    int w = threadIdx.x >> 5, l = threadIdx.x & 31;
    if (l == 0) { red[0][w] = s; red[1][w] = s2; }
    __syncthreads();
    if (threadIdx.x == 0) {
        float ts = 0.f, ts2 = 0.f;
        #pragma unroll
        for (int i = 0; i < 8; i++) { ts += red[0][i]; ts2 += red[1][i]; }
        float mu  = ts / 16384.f;
        float var = ts2 / 16384.f - mu * mu;
        red[0][0] = mu;
        red[1][0] = rsqrtf(var + 1e-5f);
    }
    __syncthreads();
    float mu = red[0][0], rstd = red[1][0];
    uint2* outp = (uint2*)(g_h + base);
    for (int q = threadIdx.x; q < 4096; q += 256) {
        float4 v = sx[q];
        int c = g * 16 + (q >> 8);
        float ga = gamma[c] * rstd;
        float be = beta[c] - mu * ga;
        outp[q] = pack4(v.x * ga + be, v.y * ga + be, v.z * ga + be, v.w * ga + be);
    }
}

// ======================= BF16 wmma GEMM, cp.async double-buffered ==========
// out[b][o][p] = (res? x : 0) + bias[o] + sum_c w[o][c]*in[b][c][p]
// Block tile 128(o) x 128(p), BK=32, 256 thr = 8 warps (4m x 2n), 2x4 frags each.
template <bool RES>
__global__ void gemm_wmma(const bf16* __restrict__ in, const bf16* __restrict__ w,
                          const float* __restrict__ bias, const float* __restrict__ res,
                          void* __restrict__ outv, int OC) {
    extern __shared__ char smc[];
    bf16*  sA = (bf16*)smc;             // [2][128][40]
    bf16*  sB = (bf16*)(smc + 20480);   // [2][32][136]
    float* sC = (float*)smc;            // [128][132] epilogue overlay

    int b = blockIdx.z;
    int o0 = blockIdx.y * 128, p0 = blockIdx.x * 128;
    int tid = threadIdx.x, wid = tid >> 5;
    int wm = wid >> 1, wn = wid & 1;

    const bf16* wbase = w + (size_t)o0 * C_;
    const bf16* ibase = in + ((size_t)b * C_) * HW + p0;

    wmma::fragment<wmma::accumulator, 16, 16, 16, float> acc[2][4];
    #pragma unroll
    for (int i = 0; i < 2; i++)
        #pragma unroll
        for (int j = 0; j < 4; j++) wmma::fill_fragment(acc[i][j], 0.0f);

    auto issue = [&](int it, int bu) {
        int c0 = it * 32;
        bf16* dA = sA + bu * (128 * 40);
        bf16* dB = sB + bu * (32 * 136);
        #pragma unroll
        for (int u = 0; u < 2; u++) {
            int idx = tid + u * 256;
            int o = idx >> 2, kq = (idx & 3) * 8;
            cp16(dA + o * 40 + kq, wbase + (size_t)o * C_ + c0 + kq);
            int k = idx >> 4, jq = (idx & 15) * 8;
            cp16(dB + k * 136 + jq, ibase + (size_t)(c0 + k) * HW + jq);
        }
        cp_commit();
    };

    issue(0, 0);
    for (int it = 0; it < 16; it++) {
        int cur = it & 1;
        cp_wait0();
        __syncthreads();
        if (it < 15) issue(it + 1, cur ^ 1);
        bf16* A  = sA + cur * (128 * 40);
        bf16* Bt = sB + cur * (32 * 136);
        #pragma unroll
        for (int kk = 0; kk < 32; kk += 16) {
            wmma::fragment<wmma::matrix_a, 16, 16, 16, bf16, wmma::row_major> af[2];
            wmma::fragment<wmma::matrix_b, 16, 16, 16, bf16, wmma::row_major> bfr[4];
            #pragma unroll
            for (int mi = 0; mi < 2; mi++)
                wmma::load_matrix_sync(af[mi], &A[(wm * 32 + mi * 16) * 40 + kk], 40);
            #pragma unroll
            for (int ni = 0; ni < 4; ni++)
                wmma::load_matrix_sync(bfr[ni], &Bt[kk * 136 + wn * 64 + ni * 16], 136);
            #pragma unroll
            for (int mi = 0; mi < 2; mi++)
                #pragma unroll
                for (int ni = 0; ni < 4; ni++)
                    wmma::mma_sync(acc[mi][ni], af[mi], bfr[ni], acc[mi][ni]);
        }
        __syncthreads();
    }

    #pragma unroll
    for (int mi = 0; mi < 2; mi++)
        #pragma unroll
        for (int ni = 0; ni < 4; ni++)
            wmma::store_matrix_sync(&sC[(wm * 32 + mi * 16) * 132 + wn * 64 + ni * 16],
                                    acc[mi][ni], 132, wmma::mem_row_major);
    __syncthreads();

    #pragma unroll
    for (int u = 0; u < 16; u++) {
        int idx = tid + u * 256;
        int o = idx >> 5, pq = (idx & 31) * 4;
        float4 v = *(float4*)&sC[o * 132 + pq];
        float bb = bias[o0 + o];
        size_t oaddr = ((size_t)b * OC + o0 + o) * HW + p0 + pq;
        v.x += bb; v.y += bb; v.z += bb; v.w += bb;
        if (RES) {
            float4 rv = *(const float4*)&res[oaddr];
            v.x += rv.x; v.y += rv.y; v.z += rv.z; v.w += rv.w;
            *(float4*)&((float*)outv)[oaddr] = v;
        } else {
            *(uint2*)&((bf16*)outv)[oaddr] = pack4(v.x, v.y, v.z, v.w);
        }
    }
}

// ======================= BF16 wmma attention, cp.async K/V =======================
__global__ void attn_wmma() {
    extern __shared__ char smc[];
    bf16*  sQ = (bf16*)smc;              // [64][72]
    bf16*  sK = (bf16*)(smc + 9216);     // [2][64][72]
    bf16*  sV = (bf16*)(smc + 27648);    // [2][64][72]
    bf16*  sP = (bf16*)(smc + 46080);    // [64][72]
    float* sS = (float*)(smc + 55296);   // [64][68] fp32
    float* sL = (float*)(smc + 72704);   // [64]

    int bh = blockIdx.y;
    int b = bh >> 3, nh = bh & 7;
    int i0 = blockIdx.x * 64;
    int tid = threadIdx.x, wid = tid >> 5;
    int wr = wid >> 1;            // 4 row strips of 16
    int wc = (wid & 1) * 32;      // 2 col strips of 32

    const bf16* qptr = g_qkv + ((size_t)(b * OC_QKV + nh * DH)) * HW + i0;
    const bf16* kptr = g_qkv + ((size_t)(b * OC_QKV + C_ + nh * DH)) * HW;
    const bf16* vptr = g_qkv + ((size_t)(b * OC_QKV + 2 * C_ + nh * DH)) * HW;

    auto issueKV = [&](int it, int bu) {
        int j0 = it * 64;
        bf16* dK = sK + bu * (64 * 72);
        bf16* dV = sV + bu * (64 * 72);
        #pragma unroll
        for (int u = 0; u < 2; u++) {
            int idx = tid + u * 256;
            int d = idx >> 3, jq = (idx & 7) * 8;
            cp16(dK + d * 72 + jq, kptr + (size_t)d * HW + j0 + jq);
            cp16(dV + d * 72 + jq, vptr + (size_t)d * HW + j0 + jq);
        }
        cp_commit();
    };

    issueKV(0, 0);

    // Q transposed (i-major), pre-scaled by DH^-0.5 = 0.125
    #pragma unroll
    for (int e = tid; e < 4096; e += 256) {
        int d = e >> 6, i = e & 63;
        float q = __bfloat162float(qptr[(size_t)d * HW + i]) * 0.125f;
        sQ[i * 72 + d] = __float2bfloat16(q);
    }

    wmma::fragment<wmma::accumulator, 16, 16, 16, float> acc_o[2];
    #pragma unroll
    for (int ci = 0; ci < 2; ci++) wmma::fill_fragment(acc_o[ci], 0.0f);
    float rsum = 0.f;
    int row = tid >> 2, q4 = (tid & 3) * 16;

    for (int it = 0; it < 16; it++) {
        int cur = it & 1;
        cp_wait0();
        __syncthreads();
        if (it < 15) issueKV(it + 1, cur ^ 1);
        bf16* K = sK + cur * (64 * 72);
        bf16* V = sV + cur * (64 * 72);

        // S = Q K^T
        wmma::fragment<wmma::accumulator, 16, 16, 16, float> acc_s[2];
        #pragma unroll
        for (int ci = 0; ci < 2; ci++) wmma::fill_fragment(acc_s[ci], 0.0f);
        #pragma unroll
        for (int kk = 0; kk < 64; kk += 16) {
            wmma::fragment<wmma::matrix_a, 16, 16, 16, bf16, wmma::row_major> af;
            wmma::load_matrix_sync(af, &sQ[(wr * 16) * 72 + kk], 72);
            #pragma unroll
            for (int ci = 0; ci < 2; ci++) {
                wmma::fragment<wmma::matrix_b, 16, 16, 16, bf16, wmma::row_major> bfr;
                wmma::load_matrix_sync(bfr, &K[kk * 72 + wc + ci * 16], 72);
                wmma::mma_sync(acc_s[ci], af, bfr, acc_s[ci]);
            }
        }
        #pragma unroll
        for (int ci = 0; ci < 2; ci++)
            wmma::store_matrix_sync(&sS[(wr * 16) * 68 + wc + ci * 16], acc_s[ci], 68,
                                    wmma::mem_row_major);
        __syncthreads();

        // exp + rowsum; stage P bf16
        #pragma unroll
        for (int z = 0; z < 16; z++) {
            float p = __expf(sS[row * 68 + q4 + z]);
            rsum += p;
            sP[row * 72 + q4 + z] = __float2bfloat16(p);
        }
        __syncthreads();

        // O += P V
        #pragma unroll
        for (int kk = 0; kk < 64; kk += 16) {
            wmma::fragment<wmma::matrix_a, 16, 16, 16, bf16, wmma::row_major> af;
            wmma::load_matrix_sync(af, &sP[(wr * 16) * 72 + kk], 72);
            #pragma unroll
            for (int ci = 0; ci < 2; ci++) {
                wmma::fragment<wmma::matrix_b, 16, 16, 16, bf16, wmma::col_major> bfr;
                wmma::load_matrix_sync(bfr, &V[(wc + ci * 16) * 72 + kk], 72);
                wmma::mma_sync(acc_o[ci], af, bfr, acc_o[ci]);
            }
        }
    }

    rsum += __shfl_xor_sync(~0u, rsum, 1);
    rsum += __shfl_xor_sync(~0u, rsum, 2);
    if ((tid & 3) == 0) sL[row] = 1.0f / rsum;
    __syncthreads();

    #pragma unroll
    for (int ci = 0; ci < 2; ci++)
        wmma::store_matrix_sync(&sS[(wr * 16) * 68 + wc + ci * 16], acc_o[ci], 68,
                                wmma::mem_row_major);
    __syncthreads();

    // write bf16, torch-faithful reshape: c = nh*64 + (i>>4), p = (i&15)*64 + d
    {
        int il = tid >> 2, dq = (tid & 3) * 16;
        float inv = sL[il];
        int i = i0 + il;
        int c_out = nh * 64 + (i >> 4);
        int p = (i & 15) * 64 + dq;
        size_t base = ((size_t)(b * C_ + c_out)) * HW + p;
        #pragma unroll
        for (int z = 0; z < 4; z++) {
            float4 v = *(float4*)&sS[il * 68 + dq + z * 4];
            *(uint2*)&g_att[base + z * 4] =
                pack4(v.x * inv, v.y * inv, v.z * inv, v.w * inv);
        }
    }
}

// ============================ launch ============================
extern "C" void kernel_launch(void* const* d_in, const int* in_sizes, int n_in,
                              void* d_out, int out_size) {
    const float* x      = (const float*)d_in[0];
    const float* gamma  = (const float*)d_in[1];
    const float* beta   = (const float*)d_in[2];
    const float* qkv_w  = (const float*)d_in[3];
    const float* qkv_b  = (const float*)d_in[4];
    const float* proj_w = (const float*)d_in[5];
    const float* proj_b = (const float*)d_in[6];
    float* out = (float*)d_out;

    void *p_h, *p_qkv, *p_att, *p_wq, *p_wp;
    cudaGetSymbolAddress(&p_h, g_h);
    cudaGetSymbolAddress(&p_qkv, g_qkv);
    cudaGetSymbolAddress(&p_att, g_att);
    cudaGetSymbolAddress(&p_wq, g_wq);
    cudaGetSymbolAddress(&p_wp, g_wp);

    const int GEMM_SMEM = 67584;   // max(tiles 37888, epilogue 128*132*4)
    const int ATTN_SMEM = 72960;
    const int GN_SMEM   = 65536;
    cudaFuncSetAttribute(gemm_wmma<false>,
                         cudaFuncAttributeMaxDynamicSharedMemorySize, GEMM_SMEM);
    cudaFuncSetAttribute(gemm_wmma<true>,
                         cudaFuncAttributeMaxDynamicSharedMemorySize, GEMM_SMEM);
    cudaFuncSetAttribute(attn_wmma,
                         cudaFuncAttributeMaxDynamicSharedMemorySize, ATTN_SMEM);
    cudaFuncSetAttribute(groupnorm_kernel,
                         cudaFuncAttributeMaxDynamicSharedMemorySize, GN_SMEM);

    // 0. weights -> bf16
    wconv<<<768, 256>>>(qkv_w, (bf16*)p_wq, 196608);
    wconv<<<256, 256>>>(proj_w, (bf16*)p_wp, 65536);

    // 1. GroupNorm -> bf16 h
    groupnorm_kernel<<<256, 256, GN_SMEM>>>(x, gamma, beta);

    // 2. QKV
    gemm_wmma<false><<<dim3(8, 12, B_), 256, GEMM_SMEM>>>(
        (const bf16*)p_h, (const bf16*)p_wq, qkv_b, nullptr, p_qkv, OC_QKV);

    // 3. Attention
    attn_wmma<<<dim3(16, B_ * NH), 256, ATTN_SMEM>>>();

    // 4. out = x + proj(att)
    gemm_wmma<true><<<dim3(8, 4, B_), 256, GEMM_SMEM>>>(
        (const bf16*)p_att, (const bf16*)p_wp, proj_b, x, out, C_);
}

// round 5
// speedup vs baseline: 5.4987x; 1.6027x over previous
#include <cuda_runtime.h>
#include <cuda_bf16.h>
#include <mma.h>
using namespace nvcuda;

#define B_ 8
#define C_ 512
#define HW 1024
#define NH 8
#define DH 64
#define OC_QKV 1536

typedef __nv_bfloat16 bf16;

// -------- scratch (static device globals; no allocation) --------
__device__ bf16 g_h[B_ * C_ * HW];
__device__ bf16 g_qkv[B_ * OC_QKV * HW];
__device__ bf16 g_att[B_ * C_ * HW];
__device__ bf16 g_wq[OC_QKV * C_];
__device__ bf16 g_wp[C_ * C_];

// -------- helpers --------
__device__ __forceinline__ void cp16(void* dst, const void* src) {
    unsigned d = (unsigned)__cvta_generic_to_shared(dst);
    asm volatile("cp.async.cg.shared.global [%0], [%1], 16;\n" :: "r"(d), "l"(src));
}
__device__ __forceinline__ void cp_commit() { asm volatile("cp.async.commit_group;\n" ::); }
__device__ __forceinline__ void cp_wait0()  { asm volatile("cp.async.wait_group 0;\n" ::); }
__device__ __forceinline__ void cp_wait1()  { asm volatile("cp.async.wait_group 1;\n" ::); }

__device__ __forceinline__ uint2 pack4(float a, float b, float c, float d) {
    __nv_bfloat162 lo = __floats2bfloat162_rn(a, b);
    __nv_bfloat162 hi = __floats2bfloat162_rn(c, d);
    uint2 r; r.x = *(unsigned*)&lo; r.y = *(unsigned*)&hi; return r;
}
__device__ __forceinline__ unsigned packu(float a, float b) {
    __nv_bfloat162 t = __floats2bfloat162_rn(a, b);
    return *(unsigned*)&t;
}
__device__ __forceinline__ void mma16816(float* c, const unsigned* a, unsigned b0, unsigned b1) {
    asm volatile("mma.sync.aligned.m16n8k16.row.col.f32.bf16.bf16.f32 "
                 "{%0,%1,%2,%3}, {%4,%5,%6,%7}, {%8,%9}, {%0,%1,%2,%3};\n"
                 : "+f"(c[0]), "+f"(c[1]), "+f"(c[2]), "+f"(c[3])
                 : "r"(a[0]), "r"(a[1]), "r"(a[2]), "r"(a[3]), "r"(b0), "r"(b1));
}
__device__ __forceinline__ void ldsm4(unsigned* r, unsigned addr) {
    asm volatile("ldmatrix.sync.aligned.m8n8.x4.shared.b16 {%0,%1,%2,%3}, [%4];\n"
                 : "=r"(r[0]), "=r"(r[1]), "=r"(r[2]), "=r"(r[3]) : "r"(addr));
}
__device__ __forceinline__ void ldsm2(unsigned& r0, unsigned& r1, unsigned addr) {
    asm volatile("ldmatrix.sync.aligned.m8n8.x2.shared.b16 {%0,%1}, [%2];\n"
                 : "=r"(r0), "=r"(r1) : "r"(addr));
}
__device__ __forceinline__ void ldsm2t(unsigned& r0, unsigned& r1, unsigned addr) {
    asm volatile("ldmatrix.sync.aligned.m8n8.x2.trans.shared.b16 {%0,%1}, [%2];\n"
                 : "=r"(r0), "=r"(r1) : "r"(addr));
}

// ============== weight fp32 -> bf16 ==============
__global__ void wconv(const float* __restrict__ s, bf16* __restrict__ d, int n4) {
    int i = blockIdx.x * 256 + threadIdx.x;
    if (i < n4) {
        float4 v = ((const float4*)s)[i];
        ((uint2*)d)[i] = pack4(v.x, v.y, v.z, v.w);
    }
}

// ============================ GroupNorm ============================
__global__ void groupnorm_kernel(const float* __restrict__ x,
                                 const float* __restrict__ gamma,
                                 const float* __restrict__ beta) {
    extern __shared__ float4 sx[];
    int bg = blockIdx.x;
    int b = bg >> 5, g = bg & 31;
    size_t base = ((size_t)(b * C_ + g * 16)) * HW;
    const float4* xin = (const float4*)(x + base);

    float s = 0.f, s2 = 0.f;
    for (int q = threadIdx.x; q < 4096; q += 256) {
        float4 v = xin[q];
        sx[q] = v;
        s  += v.x + v.y + v.z + v.w;
        s2 += v.x * v.x + v.y * v.y + v.z * v.z + v.w * v.w;
    }
    __shared__ float red[2][8];
    #pragma unroll
    for (int o = 16; o; o >>= 1) {
        s  += __shfl_xor_sync(~0u, s, o);
        s2 += __shfl_xor_sync(~0u, s2, o);
    }
    int w = threadIdx.x >> 5, l = threadIdx.x & 31;
    if (l == 0) { red[0][w] = s; red[1][w] = s2; }
    __syncthreads();
    if (threadIdx.x == 0) {
        float ts = 0.f, ts2 = 0.f;
        #pragma unroll
        for (int i = 0; i < 8; i++) { ts += red[0][i]; ts2 += red[1][i]; }
        float mu  = ts / 16384.f;
        float var = ts2 / 16384.f - mu * mu;
        red[0][0] = mu;
        red[1][0] = rsqrtf(var + 1e-5f);
    }
    __syncthreads();
    float mu = red[0][0], rstd = red[1][0];
    uint2* outp = (uint2*)(g_h + base);
    for (int q = threadIdx.x; q < 4096; q += 256) {
        float4 v = sx[q];
        int c = g * 16 + (q >> 8);
        float ga = gamma[c] * rstd;
        float be = beta[c] - mu * ga;
        outp[q] = pack4(v.x * ga + be, v.y * ga + be, v.z * ga + be, v.w * ga + be);
    }
}

// ======================= BF16 wmma GEMM, 3-stage cp.async ==========
// Block tile 128(o) x 128(p), BK=32, 8 warps (4m x 2n), 2x4 wmma frags each.
template <bool RES>
__global__ __launch_bounds__(256, 2)
void gemm_wmma(const bf16* __restrict__ in, const bf16* __restrict__ w,
               const float* __restrict__ bias, const float* __restrict__ res,
               void* __restrict__ outv, int OC) {
    extern __shared__ char smc[];
    bf16*  sA = (bf16*)smc;             // [3][128][40]
    bf16*  sB = (bf16*)(smc + 30720);   // [3][32][136]
    float* sC = (float*)smc;            // [128][132] epilogue overlay

    int b = blockIdx.z;
    int o0 = blockIdx.y * 128, p0 = blockIdx.x * 128;
    int tid = threadIdx.x, wid = tid >> 5;
    int wm = wid >> 1, wn = wid & 1;

    const bf16* wbase = w + (size_t)o0 * C_;
    const bf16* ibase = in + ((size_t)b * C_) * HW + p0;

    wmma::fragment<wmma::accumulator, 16, 16, 16, float> acc[2][4];
    #pragma unroll
    for (int i = 0; i < 2; i++)
        #pragma unroll
        for (int j = 0; j < 4; j++) wmma::fill_fragment(acc[i][j], 0.0f);

    auto issue = [&](int it) {
        int bu = it % 3, c0 = it * 32;
        bf16* dA = sA + bu * 5120;
        bf16* dB = sB + bu * 4352;
        #pragma unroll
        for (int u = 0; u < 2; u++) {
            int idx = tid + u * 256;
            int o = idx >> 2, kq = (idx & 3) * 8;
            cp16(dA + o * 40 + kq, wbase + (size_t)o * C_ + c0 + kq);
            int k = idx >> 4, jq = (idx & 15) * 8;
            cp16(dB + k * 136 + jq, ibase + (size_t)(c0 + k) * HW + jq);
        }
        cp_commit();
    };

    issue(0); issue(1);
    for (int it = 0; it < 16; it++) {
        if (it < 15) cp_wait1(); else cp_wait0();
        __syncthreads();
        if (it + 2 < 16) issue(it + 2);
        int bu = it % 3;
        bf16* A  = sA + bu * 5120;
        bf16* Bt = sB + bu * 4352;
        #pragma unroll
        for (int kk = 0; kk < 32; kk += 16) {
            wmma::fragment<wmma::matrix_a, 16, 16, 16, bf16, wmma::row_major> af[2];
            wmma::fragment<wmma::matrix_b, 16, 16, 16, bf16, wmma::row_major> bfr[4];
            #pragma unroll
            for (int mi = 0; mi < 2; mi++)
                wmma::load_matrix_sync(af[mi], &A[(wm * 32 + mi * 16) * 40 + kk], 40);
            #pragma unroll
            for (int ni = 0; ni < 4; ni++)
                wmma::load_matrix_sync(bfr[ni], &Bt[kk * 136 + wn * 64 + ni * 16], 136);
            #pragma unroll
            for (int mi = 0; mi < 2; mi++)
                #pragma unroll
                for (int ni = 0; ni < 4; ni++)
                    wmma::mma_sync(acc[mi][ni], af[mi], bfr[ni], acc[mi][ni]);
        }
    }
    __syncthreads();

    #pragma unroll
    for (int mi = 0; mi < 2; mi++)
        #pragma unroll
        for (int ni = 0; ni < 4; ni++)
            wmma::store_matrix_sync(&sC[(wm * 32 + mi * 16) * 132 + wn * 64 + ni * 16],
                                    acc[mi][ni], 132, wmma::mem_row_major);
    __syncthreads();

    #pragma unroll
    for (int u = 0; u < 16; u++) {
        int idx = tid + u * 256;
        int o = idx >> 5, pq = (idx & 31) * 4;
        float4 v = *(float4*)&sC[o * 132 + pq];
        float bb = bias[o0 + o];
        size_t oaddr = ((size_t)b * OC + o0 + o) * HW + p0 + pq;
        v.x += bb; v.y += bb; v.z += bb; v.w += bb;
        if (RES) {
            float4 rv = *(const float4*)&res[oaddr];
            v.x += rv.x; v.y += rv.y; v.z += rv.z; v.w += rv.w;
            *(float4*)&((float*)outv)[oaddr] = v;
        } else {
            *(uint2*)&((bf16*)outv)[oaddr] = pack4(v.x, v.y, v.z, v.w);
        }
    }
}

// ======================= Raw-mma FA2-style attention =======================
// Block: (b,head), 128 Q rows, 8 warps; warp w owns rows 16w..16w+15.
// S/P/exp/rowsum live in registers; one __syncthreads per j-tile (K/V ring).
__global__ __launch_bounds__(256, 2) void attn_mma() {
    extern __shared__ char smc[];
    bf16* sQ = (bf16*)smc;                    // [128][72]
    bf16* sK = (bf16*)(smc + 18432);          // [3][64][72]
    bf16* sV = (bf16*)(smc + 18432 + 27648);  // [3][64][72]

    int bh = blockIdx.y;
    int b = bh >> 3, nh = bh & 7;
    int i0 = blockIdx.x * 128;
    int tid = threadIdx.x, wid = tid >> 5, lane = tid & 31;

    const bf16* qptr = g_qkv + ((size_t)(b * OC_QKV + nh * DH)) * HW + i0;
    const bf16* kptr = g_qkv + ((size_t)(b * OC_QKV + C_ + nh * DH)) * HW;
    const bf16* vptr = g_qkv + ((size_t)(b * OC_QKV + 2 * C_ + nh * DH)) * HW;

    auto issueKV = [&](int it) {
        int bu = it % 3, j0 = it * 64;
        bf16* dK = sK + bu * 4608;
        bf16* dV = sV + bu * 4608;
        #pragma unroll
        for (int u = 0; u < 2; u++) {
            int idx = tid + u * 256;
            int d = idx >> 3, jq = (idx & 7) * 8;
            cp16(dK + d * 72 + jq, kptr + (size_t)d * HW + j0 + jq);
            cp16(dV + d * 72 + jq, vptr + (size_t)d * HW + j0 + jq);
        }
        cp_commit();
    };

    issueKV(0); issueKV(1);

    // stage Q transposed [i][d], pre-scaled by DH^-0.5 = 0.125 (exact in bf16)
    for (int e = tid; e < 1024; e += 256) {
        int d = e >> 4, i8 = (e & 15) * 8;
        uint4 v = *(const uint4*)&qptr[(size_t)d * HW + i8];
        bf16 tmp[8]; *(uint4*)tmp = v;
        #pragma unroll
        for (int z = 0; z < 8; z++)
            sQ[(i8 + z) * 72 + d] = __float2bfloat16(__bfloat162float(tmp[z]) * 0.125f);
    }
    __syncthreads();

    // load Q fragments (4 k-steps over d), keep in registers
    unsigned aq[4][4];
    {
        unsigned qb = (unsigned)__cvta_generic_to_shared(sQ);
        unsigned rowaddr = qb + ((wid * 16 + (lane & 15)) * 72 + (lane >> 4) * 8) * 2;
        #pragma unroll
        for (int kk = 0; kk < 4; kk++) ldsm4(aq[kk], rowaddr + kk * 32);
    }

    float co[8][4] = {};          // O strip accumulators (n-chunks over d)
    float rs0 = 0.f, rs1 = 0.f;   // rowsum partials for rows lane>>2, +8
    unsigned kb0 = (unsigned)__cvta_generic_to_shared(sK);
    unsigned vb0 = (unsigned)__cvta_generic_to_shared(sV);
    int l16 = lane & 15, lr8 = lane & 7, half8 = ((lane >> 3) & 1) * 8;

    for (int it = 0; it < 16; it++) {
        if (it < 15) cp_wait1(); else cp_wait0();
        __syncthreads();
        if (it + 2 < 16) issueKV(it + 2);
        unsigned kb = kb0 + (it % 3) * 9216;
        unsigned vb = vb0 + (it % 3) * 9216;

        // S = Q K^T : 8 n-chunks of 8 cols, 4 k-steps over d
        float cs[8][4] = {};
        #pragma unroll
        for (int kk = 0; kk < 4; kk++) {
            unsigned ka = kb + ((kk * 16 + l16) * 72) * 2;
            #pragma unroll
            for (int jn = 0; jn < 8; jn++) {
                unsigned b0x, b1x;
                ldsm2t(b0x, b1x, ka + jn * 16);
                mma16816(cs[jn], aq[kk], b0x, b1x);
            }
        }

        // exp in registers; pack P pairs as A-operands for PV
        unsigned ap[4][4];
        #pragma unroll
        for (int t = 0; t < 4; t++) {
            float p0 = __expf(cs[2 * t][0]),     p1 = __expf(cs[2 * t][1]);
            float p2 = __expf(cs[2 * t][2]),     p3 = __expf(cs[2 * t][3]);
            float q0 = __expf(cs[2 * t + 1][0]), q1 = __expf(cs[2 * t + 1][1]);
            float q2 = __expf(cs[2 * t + 1][2]), q3 = __expf(cs[2 * t + 1][3]);
            rs0 += p0 + p1 + q0 + q1;
            rs1 += p2 + p3 + q2 + q3;
            ap[t][0] = packu(p0, p1); ap[t][1] = packu(p2, p3);
            ap[t][2] = packu(q0, q1); ap[t][3] = packu(q2, q3);
        }

        // O += P V : 4 k-steps over j, 8 n-chunks over d
        #pragma unroll
        for (int t = 0; t < 4; t++) {
            unsigned va = vb + (lr8 * 72 + t * 16 + half8) * 2;
            #pragma unroll
            for (int dn = 0; dn < 8; dn++) {
                unsigned b0x, b1x;
                ldsm2(b0x, b1x, va + dn * 8 * 72 * 2);
                mma16816(co[dn], ap[t], b0x, b1x);
            }
        }
    }

    // rowsum reduce within quad (lanes sharing the same rows)
    rs0 += __shfl_xor_sync(~0u, rs0, 1); rs0 += __shfl_xor_sync(~0u, rs0, 2);
    rs1 += __shfl_xor_sync(~0u, rs1, 1); rs1 += __shfl_xor_sync(~0u, rs1, 2);
    float inv0 = 1.f / rs0, inv1 = 1.f / rs1;

    // write O from registers; torch-faithful reshape:
    // (b,nh,i,d) -> c = nh*64 + (i>>4), p = (i&15)*64 + d
    int ir0 = i0 + wid * 16 + (lane >> 2);
    int ir1 = ir0 + 8;
    size_t a0 = ((size_t)(b * C_ + nh * 64 + (ir0 >> 4))) * HW + (ir0 & 15) * 64;
    size_t a1 = ((size_t)(b * C_ + nh * 64 + (ir1 >> 4))) * HW + (ir1 & 15) * 64;
    #pragma unroll
    for (int dn = 0; dn < 8; dn++) {
        int d = dn * 8 + (lane & 3) * 2;
        *(unsigned*)&g_att[a0 + d] = packu(co[dn][0] * inv0, co[dn][1] * inv0);
        *(unsigned*)&g_att[a1 + d] = packu(co[dn][2] * inv1, co[dn][3] * inv1);
    }
}

// ============================ launch ============================
extern "C" void kernel_launch(void* const* d_in, const int* in_sizes, int n_in,
                              void* d_out, int out_size) {
    const float* x      = (const float*)d_in[0];
    const float* gamma  = (const float*)d_in[1];
    const float* beta   = (const float*)d_in[2];
    const float* qkv_w  = (const float*)d_in[3];
    const float* qkv_b  = (const float*)d_in[4];
    const float* proj_w = (const float*)d_in[5];
    const float* proj_b = (const float*)d_in[6];
    float* out = (float*)d_out;

    void *p_h, *p_qkv, *p_att, *p_wq, *p_wp;
    cudaGetSymbolAddress(&p_h, g_h);
    cudaGetSymbolAddress(&p_qkv, g_qkv);
    cudaGetSymbolAddress(&p_att, g_att);
    cudaGetSymbolAddress(&p_wq, g_wq);
    cudaGetSymbolAddress(&p_wp, g_wp);

    const int GEMM_SMEM = 67584;
    const int ATTN_SMEM = 18432 + 2 * 27648;   // 73728
    const int GN_SMEM   = 65536;
    cudaFuncSetAttribute(gemm_wmma<false>,
                         cudaFuncAttributeMaxDynamicSharedMemorySize, GEMM_SMEM);
    cudaFuncSetAttribute(gemm_wmma<true>,
                         cudaFuncAttributeMaxDynamicSharedMemorySize, GEMM_SMEM);
    cudaFuncSetAttribute(attn_mma,
                         cudaFuncAttributeMaxDynamicSharedMemorySize, ATTN_SMEM);
    cudaFuncSetAttribute(groupnorm_kernel,
                         cudaFuncAttributeMaxDynamicSharedMemorySize, GN_SMEM);

    wconv<<<768, 256>>>(qkv_w, (bf16*)p_wq, 196608);
    wconv<<<256, 256>>>(proj_w, (bf16*)p_wp, 65536);

    groupnorm_kernel<<<256, 256, GN_SMEM>>>(x, gamma, beta);

    gemm_wmma<false><<<dim3(8, 12, B_), 256, GEMM_SMEM>>>(
        (const bf16*)p_h, (const bf16*)p_wq, qkv_b, nullptr, p_qkv, OC_QKV);

    attn_mma<<<dim3(8, 64), 256, ATTN_SMEM>>>();

    gemm_wmma<true><<<dim3(8, 4, B_), 256, GEMM_SMEM>>>(
        (const bf16*)p_att, (const bf16*)p_wp, proj_b, x, out, C_);
}

// round 6
// speedup vs baseline: 6.8070x; 1.2379x over previous
#include <cuda_runtime.h>
#include <cuda_bf16.h>

#define B_ 8
#define C_ 512
#define HW 1024
#define NH 8
#define DH 64
#define OC_QKV 1536

typedef __nv_bfloat16 bf16;

// -------- scratch (static device globals; no allocation) --------
__device__ bf16 g_h[B_ * C_ * HW];
__device__ bf16 g_qkv[B_ * OC_QKV * HW];
__device__ bf16 g_att[B_ * C_ * HW];
__device__ bf16 g_wq[OC_QKV * C_];
__device__ bf16 g_wp[C_ * C_];

// -------- helpers --------
__device__ __forceinline__ void cp16(void* dst, const void* src) {
    unsigned d = (unsigned)__cvta_generic_to_shared(dst);
    asm volatile("cp.async.cg.shared.global [%0], [%1], 16;\n" :: "r"(d), "l"(src));
}
__device__ __forceinline__ void cp_commit() { asm volatile("cp.async.commit_group;\n" ::); }
__device__ __forceinline__ void cp_wait0()  { asm volatile("cp.async.wait_group 0;\n" ::); }
__device__ __forceinline__ void cp_wait1()  { asm volatile("cp.async.wait_group 1;\n" ::); }
__device__ __forceinline__ void cp_wait3()  { asm volatile("cp.async.wait_group 3;\n" ::); }

__device__ __forceinline__ uint2 pack4(float a, float b, float c, float d) {
    __nv_bfloat162 lo = __floats2bfloat162_rn(a, b);
    __nv_bfloat162 hi = __floats2bfloat162_rn(c, d);
    uint2 r; r.x = *(unsigned*)&lo; r.y = *(unsigned*)&hi; return r;
}
__device__ __forceinline__ unsigned packu(float a, float b) {
    __nv_bfloat162 t = __floats2bfloat162_rn(a, b);
    return *(unsigned*)&t;
}
__device__ __forceinline__ void mma16816(float* c, const unsigned* a, unsigned b0, unsigned b1) {
    asm volatile("mma.sync.aligned.m16n8k16.row.col.f32.bf16.bf16.f32 "
                 "{%0,%1,%2,%3}, {%4,%5,%6,%7}, {%8,%9}, {%0,%1,%2,%3};\n"
                 : "+f"(c[0]), "+f"(c[1]), "+f"(c[2]), "+f"(c[3])
                 : "r"(a[0]), "r"(a[1]), "r"(a[2]), "r"(a[3]), "r"(b0), "r"(b1));
}
__device__ __forceinline__ void ldsm4(unsigned* r, unsigned addr) {
    asm volatile("ldmatrix.sync.aligned.m8n8.x4.shared.b16 {%0,%1,%2,%3}, [%4];\n"
                 : "=r"(r[0]), "=r"(r[1]), "=r"(r[2]), "=r"(r[3]) : "r"(addr));
}
__device__ __forceinline__ void ldsm4t(unsigned* r, unsigned addr) {
    asm volatile("ldmatrix.sync.aligned.m8n8.x4.trans.shared.b16 {%0,%1,%2,%3}, [%4];\n"
                 : "=r"(r[0]), "=r"(r[1]), "=r"(r[2]), "=r"(r[3]) : "r"(addr));
}
__device__ __forceinline__ void ldsm2(unsigned& r0, unsigned& r1, unsigned addr) {
    asm volatile("ldmatrix.sync.aligned.m8n8.x2.shared.b16 {%0,%1}, [%2];\n"
                 : "=r"(r0), "=r"(r1) : "r"(addr));
}
__device__ __forceinline__ void ldsm2t(unsigned& r0, unsigned& r1, unsigned addr) {
    asm volatile("ldmatrix.sync.aligned.m8n8.x2.trans.shared.b16 {%0,%1}, [%2];\n"
                 : "=r"(r0), "=r"(r1) : "r"(addr));
}

// ============== weight fp32 -> bf16 ==============
__global__ void wconv(const float* __restrict__ s, bf16* __restrict__ d, int n4) {
    int i = blockIdx.x * 256 + threadIdx.x;
    if (i < n4) {
        float4 v = ((const float4*)s)[i];
        ((uint2*)d)[i] = pack4(v.x, v.y, v.z, v.w);
    }
}

// ============================ GroupNorm ============================
__global__ void groupnorm_kernel(const float* __restrict__ x,
                                 const float* __restrict__ gamma,
                                 const float* __restrict__ beta) {
    extern __shared__ float4 sx[];
    int bg = blockIdx.x;
    int b = bg >> 5, g = bg & 31;
    size_t base = ((size_t)(b * C_ + g * 16)) * HW;
    const float4* xin = (const float4*)(x + base);

    float s = 0.f, s2 = 0.f;
    for (int q = threadIdx.x; q < 4096; q += 256) {
        float4 v = xin[q];
        sx[q] = v;
        s  += v.x + v.y + v.z + v.w;
        s2 += v.x * v.x + v.y * v.y + v.z * v.z + v.w * v.w;
    }
    __shared__ float red[2][8];
    #pragma unroll
    for (int o = 16; o; o >>= 1) {
        s  += __shfl_xor_sync(~0u, s, o);
        s2 += __shfl_xor_sync(~0u, s2, o);
    }
    int w = threadIdx.x >> 5, l = threadIdx.x & 31;
    if (l == 0) { red[0][w] = s; red[1][w] = s2; }
    __syncthreads();
    if (threadIdx.x == 0) {
        float ts = 0.f, ts2 = 0.f;
        #pragma unroll
        for (int i = 0; i < 8; i++) { ts += red[0][i]; ts2 += red[1][i]; }
        float mu  = ts / 16384.f;
        float var = ts2 / 16384.f - mu * mu;
        red[0][0] = mu;
        red[1][0] = rsqrtf(var + 1e-5f);
    }
    __syncthreads();
    float mu = red[0][0], rstd = red[1][0];
    uint2* outp = (uint2*)(g_h + base);
    for (int q = threadIdx.x; q < 4096; q += 256) {
        float4 v = sx[q];
        int c = g * 16 + (q >> 8);
        float ga = gamma[c] * rstd;
        float be = beta[c] - mu * ga;
        outp[q] = pack4(v.x * ga + be, v.y * ga + be, v.z * ga + be, v.w * ga + be);
    }
}

// =============== Raw-mma GEMM, 5-stage cp.async, register epilogue ==========
// out[b][o][p] = (res? x : 0) + bias[o] + sum_c w[o][c]*in[b][c][p]
// Block 128(o) x 128(p), BK=32; 8 warps as 4(m)x2(n), warp tile 32x64.
template <bool RES>
__global__ __launch_bounds__(256, 2)
void gemm_mma(const bf16* __restrict__ in, const bf16* __restrict__ w,
              const float* __restrict__ bias, const float* __restrict__ res,
              void* __restrict__ outv, int OC) {
    extern __shared__ char smc[];
    bf16* sA = (bf16*)smc;              // [5][128][40]
    bf16* sB = (bf16*)(smc + 51200);    // [5][32][136]

    int b = blockIdx.z;
    int o0 = blockIdx.y * 128, p0 = blockIdx.x * 128;
    int tid = threadIdx.x, wid = tid >> 5, lane = tid & 31;
    int wm = wid >> 1, wn = wid & 1;
    int l16 = lane & 15, lhi = lane >> 4;

    const bf16* wbase = w + (size_t)o0 * C_;
    const bf16* ibase = in + ((size_t)b * C_) * HW + p0;

    float acc[2][8][4] = {};   // [mi 16-row][dn 8-col][frag]

    auto issue = [&](int it) {
        if (it < 16) {
            int bu = it % 5, c0 = it * 32;
            bf16* dA = sA + bu * 5120;
            bf16* dB = sB + bu * 4352;
            #pragma unroll
            for (int u = 0; u < 2; u++) {
                int idx = tid + u * 256;
                int o = idx >> 2, kq = (idx & 3) * 8;
                cp16(dA + o * 40 + kq, wbase + (size_t)o * C_ + c0 + kq);
                int k = idx >> 4, jq = (idx & 15) * 8;
                cp16(dB + k * 136 + jq, ibase + (size_t)(c0 + k) * HW + jq);
            }
        }
        cp_commit();   // empty groups on tail keep the count aligned
    };

    issue(0); issue(1); issue(2); issue(3);
    unsigned abase = (unsigned)__cvta_generic_to_shared(sA);
    unsigned bbase = (unsigned)__cvta_generic_to_shared(sB);

    for (int it = 0; it < 16; it++) {
        cp_wait3();
        __syncthreads();
        issue(it + 4);
        unsigned A  = abase + (it % 5) * 10240;
        unsigned Bb = bbase + (it % 5) * 8704;
        #pragma unroll
        for (int kk = 0; kk < 2; kk++) {
            unsigned aq[2][4];
            #pragma unroll
            for (int mi = 0; mi < 2; mi++)
                ldsm4(aq[mi], A + ((wm * 32 + mi * 16 + l16) * 40 + kk * 16) * 2 + lhi * 16);
            #pragma unroll
            for (int dn2 = 0; dn2 < 4; dn2++) {
                unsigned bq[4];
                ldsm4t(bq, Bb + ((kk * 16 + l16) * 136 + wn * 64 + dn2 * 16) * 2 + lhi * 16);
                #pragma unroll
                for (int mi = 0; mi < 2; mi++) {
                    mma16816(acc[mi][2 * dn2],     aq[mi], bq[0], bq[1]);
                    mma16816(acc[mi][2 * dn2 + 1], aq[mi], bq[2], bq[3]);
                }
            }
        }
    }

    // register epilogue: rows ro, ro+8 per mi; cols p + {0,1}
    #pragma unroll
    for (int mi = 0; mi < 2; mi++) {
        int ro = o0 + wm * 32 + mi * 16 + (lane >> 2);
        float b0 = bias[ro], b1 = bias[ro + 8];
        size_t a0 = ((size_t)b * OC + ro) * HW + p0 + wn * 64 + (lane & 3) * 2;
        size_t a1 = a0 + 8 * HW;
        #pragma unroll
        for (int dn = 0; dn < 8; dn++) {
            size_t off = dn * 8;
            if (RES) {
                float* of = (float*)outv;
                float2 r0 = *(const float2*)&res[a0 + off];
                float2 r1 = *(const float2*)&res[a1 + off];
                float2 v0 = {acc[mi][dn][0] + b0 + r0.x, acc[mi][dn][1] + b0 + r0.y};
                float2 v1 = {acc[mi][dn][2] + b1 + r1.x, acc[mi][dn][3] + b1 + r1.y};
                *(float2*)&of[a0 + off] = v0;
                *(float2*)&of[a1 + off] = v1;
            } else {
                bf16* ob = (bf16*)outv;
                *(unsigned*)&ob[a0 + off] = packu(acc[mi][dn][0] + b0, acc[mi][dn][1] + b0);
                *(unsigned*)&ob[a1 + off] = packu(acc[mi][dn][2] + b1, acc[mi][dn][3] + b1);
            }
        }
    }
}

// ======================= Raw-mma FA2-style attention =======================
__global__ __launch_bounds__(256, 2) void attn_mma() {
    extern __shared__ char smc[];
    bf16* sQ = (bf16*)smc;                    // [128][72]
    bf16* sK = (bf16*)(smc + 18432);          // [3][64][72]
    bf16* sV = (bf16*)(smc + 18432 + 27648);  // [3][64][72]

    int bh = blockIdx.y;
    int b = bh >> 3, nh = bh & 7;
    int i0 = blockIdx.x * 128;
    int tid = threadIdx.x, wid = tid >> 5, lane = tid & 31;

    const bf16* qptr = g_qkv + ((size_t)(b * OC_QKV + nh * DH)) * HW + i0;
    const bf16* kptr = g_qkv + ((size_t)(b * OC_QKV + C_ + nh * DH)) * HW;
    const bf16* vptr = g_qkv + ((size_t)(b * OC_QKV + 2 * C_ + nh * DH)) * HW;

    auto issueKV = [&](int it) {
        int bu = it % 3, j0 = it * 64;
        bf16* dK = sK + bu * 4608;
        bf16* dV = sV + bu * 4608;
        #pragma unroll
        for (int u = 0; u < 2; u++) {
            int idx = tid + u * 256;
            int d = idx >> 3, jq = (idx & 7) * 8;
            cp16(dK + d * 72 + jq, kptr + (size_t)d * HW + j0 + jq);
            cp16(dV + d * 72 + jq, vptr + (size_t)d * HW + j0 + jq);
        }
        cp_commit();
    };

    issueKV(0); issueKV(1);

    for (int e = tid; e < 1024; e += 256) {
        int d = e >> 4, i8 = (e & 15) * 8;
        uint4 v = *(const uint4*)&qptr[(size_t)d * HW + i8];
        bf16 tmp[8]; *(uint4*)tmp = v;
        #pragma unroll
        for (int z = 0; z < 8; z++)
            sQ[(i8 + z) * 72 + d] = __float2bfloat16(__bfloat162float(tmp[z]) * 0.125f);
    }
    __syncthreads();

    unsigned aq[4][4];
    {
        unsigned qb = (unsigned)__cvta_generic_to_shared(sQ);
        unsigned rowaddr = qb + ((wid * 16 + (lane & 15)) * 72 + (lane >> 4) * 8) * 2;
        #pragma unroll
        for (int kk = 0; kk < 4; kk++) ldsm4(aq[kk], rowaddr + kk * 32);
    }

    float co[8][4] = {};
    float rs0 = 0.f, rs1 = 0.f;
    unsigned kb0 = (unsigned)__cvta_generic_to_shared(sK);
    unsigned vb0 = (unsigned)__cvta_generic_to_shared(sV);
    int l16 = lane & 15, lr8 = lane & 7, half8 = ((lane >> 3) & 1) * 8;

    for (int it = 0; it < 16; it++) {
        if (it < 15) cp_wait1(); else cp_wait0();
        __syncthreads();
        if (it + 2 < 16) issueKV(it + 2);
        unsigned kb = kb0 + (it % 3) * 9216;
        unsigned vb = vb0 + (it % 3) * 9216;

        float cs[8][4] = {};
        #pragma unroll
        for (int kk = 0; kk < 4; kk++) {
            unsigned ka = kb + ((kk * 16 + l16) * 72) * 2;
            #pragma unroll
            for (int jn = 0; jn < 8; jn++) {
                unsigned b0x, b1x;
                ldsm2t(b0x, b1x, ka + jn * 16);
                mma16816(cs[jn], aq[kk], b0x, b1x);
            }
        }

        unsigned ap[4][4];
        #pragma unroll
        for (int t = 0; t < 4; t++) {
            float p0 = __expf(cs[2 * t][0]),     p1 = __expf(cs[2 * t][1]);
            float p2 = __expf(cs[2 * t][2]),     p3 = __expf(cs[2 * t][3]);
            float q0 = __expf(cs[2 * t + 1][0]), q1 = __expf(cs[2 * t + 1][1]);
            float q2 = __expf(cs[2 * t + 1][2]), q3 = __expf(cs[2 * t + 1][3]);
            rs0 += p0 + p1 + q0 + q1;
            rs1 += p2 + p3 + q2 + q3;
            ap[t][0] = packu(p0, p1); ap[t][1] = packu(p2, p3);
            ap[t][2] = packu(q0, q1); ap[t][3] = packu(q2, q3);
        }

        #pragma unroll
        for (int t = 0; t < 4; t++) {
            unsigned va = vb + (lr8 * 72 + t * 16 + half8) * 2;
            #pragma unroll
            for (int dn = 0; dn < 8; dn++) {
                unsigned b0x, b1x;
                ldsm2(b0x, b1x, va + dn * 8 * 72 * 2);
                mma16816(co[dn], ap[t], b0x, b1x);
            }
        }
    }

    rs0 += __shfl_xor_sync(~0u, rs0, 1); rs0 += __shfl_xor_sync(~0u, rs0, 2);
    rs1 += __shfl_xor_sync(~0u, rs1, 1); rs1 += __shfl_xor_sync(~0u, rs1, 2);
    float inv0 = 1.f / rs0, inv1 = 1.f / rs1;

    int ir0 = i0 + wid * 16 + (lane >> 2);
    int ir1 = ir0 + 8;
    size_t a0 = ((size_t)(b * C_ + nh * 64 + (ir0 >> 4))) * HW + (ir0 & 15) * 64;
    size_t a1 = ((size_t)(b * C_ + nh * 64 + (ir1 >> 4))) * HW + (ir1 & 15) * 64;
    #pragma unroll
    for (int dn = 0; dn < 8; dn++) {
        int d = dn * 8 + (lane & 3) * 2;
        *(unsigned*)&g_att[a0 + d] = packu(co[dn][0] * inv0, co[dn][1] * inv0);
        *(unsigned*)&g_att[a1 + d] = packu(co[dn][2] * inv1, co[dn][3] * inv1);
    }
}

// ============================ launch ============================
extern "C" void kernel_launch(void* const* d_in, const int* in_sizes, int n_in,
                              void* d_out, int out_size) {
    const float* x      = (const float*)d_in[0];
    const float* gamma  = (const float*)d_in[1];
    const float* beta   = (const float*)d_in[2];
    const float* qkv_w  = (const float*)d_in[3];
    const float* qkv_b  = (const float*)d_in[4];
    const float* proj_w = (const float*)d_in[5];
    const float* proj_b = (const float*)d_in[6];
    float* out = (float*)d_out;

    void *p_h, *p_qkv, *p_att, *p_wq, *p_wp;
    cudaGetSymbolAddress(&p_h, g_h);
    cudaGetSymbolAddress(&p_qkv, g_qkv);
    cudaGetSymbolAddress(&p_att, g_att);
    cudaGetSymbolAddress(&p_wq, g_wq);
    cudaGetSymbolAddress(&p_wp, g_wp);

    const int GEMM_SMEM = 94720;               // 5*(10240 + 8704)
    const int ATTN_SMEM = 18432 + 2 * 27648;   // 73728
    const int GN_SMEM   = 65536;
    cudaFuncSetAttribute(gemm_mma<false>,
                         cudaFuncAttributeMaxDynamicSharedMemorySize, GEMM_SMEM);
    cudaFuncSetAttribute(gemm_mma<true>,
                         cudaFuncAttributeMaxDynamicSharedMemorySize, GEMM_SMEM);
    cudaFuncSetAttribute(attn_mma,
                         cudaFuncAttributeMaxDynamicSharedMemorySize, ATTN_SMEM);
    cudaFuncSetAttribute(groupnorm_kernel,
                         cudaFuncAttributeMaxDynamicSharedMemorySize, GN_SMEM);

    wconv<<<768, 256>>>(qkv_w, (bf16*)p_wq, 196608);
    wconv<<<256, 256>>>(proj_w, (bf16*)p_wp, 65536);

    groupnorm_kernel<<<256, 256, GN_SMEM>>>(x, gamma, beta);

    gemm_mma<false><<<dim3(8, 12, B_), 256, GEMM_SMEM>>>(
        (const bf16*)p_h, (const bf16*)p_wq, qkv_b, nullptr, p_qkv, OC_QKV);

    attn_mma<<<dim3(8, 64), 256, ATTN_SMEM>>>();

    gemm_mma<true><<<dim3(8, 4, B_), 256, GEMM_SMEM>>>(
        (const bf16*)p_att, (const bf16*)p_wp, proj_b, x, out, C_);
}

// round 8
// speedup vs baseline: 7.0052x; 1.0291x over previous
#include <cuda_runtime.h>
#include <cuda_bf16.h>

#define B_ 8
#define C_ 512
#define HW 1024
#define NH 8
#define DH 64
#define OC_QKV 1536

typedef __nv_bfloat16 bf16;

// -------- scratch (static device globals; no allocation) --------
__device__ bf16 g_h[B_ * C_ * HW];
__device__ bf16 g_qkv[B_ * OC_QKV * HW];
__device__ bf16 g_att[B_ * C_ * HW];
__device__ bf16 g_wq[OC_QKV * C_];
__device__ bf16 g_wp[C_ * C_];

// -------- helpers --------
__device__ __forceinline__ void cp16(void* dst, const void* src) {
    unsigned d = (unsigned)__cvta_generic_to_shared(dst);
    asm volatile("cp.async.cg.shared.global [%0], [%1], 16;\n" :: "r"(d), "l"(src));
}
__device__ __forceinline__ void cp_commit() { asm volatile("cp.async.commit_group;\n" ::); }
__device__ __forceinline__ void cp_wait0()  { asm volatile("cp.async.wait_group 0;\n" ::); }
__device__ __forceinline__ void cp_wait1()  { asm volatile("cp.async.wait_group 1;\n" ::); }
__device__ __forceinline__ void cp_wait3()  { asm volatile("cp.async.wait_group 3;\n" ::); }

__device__ __forceinline__ uint2 pack4(float a, float b, float c, float d) {
    __nv_bfloat162 lo = __floats2bfloat162_rn(a, b);
    __nv_bfloat162 hi = __floats2bfloat162_rn(c, d);
    uint2 r; r.x = *(unsigned*)&lo; r.y = *(unsigned*)&hi; return r;
}
__device__ __forceinline__ unsigned packu(float a, float b) {
    __nv_bfloat162 t = __floats2bfloat162_rn(a, b);
    return *(unsigned*)&t;
}
__device__ __forceinline__ unsigned ex2_bf16x2(unsigned y) {
    unsigned r;
    asm("ex2.approx.ftz.bf16x2 %0, %1;" : "=r"(r) : "r"(y));
    return r;
}
__device__ __forceinline__ void mma16816(float* c, const unsigned* a, unsigned b0, unsigned b1) {
    asm volatile("mma.sync.aligned.m16n8k16.row.col.f32.bf16.bf16.f32 "
                 "{%0,%1,%2,%3}, {%4,%5,%6,%7}, {%8,%9}, {%0,%1,%2,%3};\n"
                 : "+f"(c[0]), "+f"(c[1]), "+f"(c[2]), "+f"(c[3])
                 : "r"(a[0]), "r"(a[1]), "r"(a[2]), "r"(a[3]), "r"(b0), "r"(b1));
}
__device__ __forceinline__ void ldsm4(unsigned* r, unsigned addr) {
    asm volatile("ldmatrix.sync.aligned.m8n8.x4.shared.b16 {%0,%1,%2,%3}, [%4];\n"
                 : "=r"(r[0]), "=r"(r[1]), "=r"(r[2]), "=r"(r[3]) : "r"(addr));
}
__device__ __forceinline__ void ldsm4t(unsigned* r, unsigned addr) {
    asm volatile("ldmatrix.sync.aligned.m8n8.x4.trans.shared.b16 {%0,%1,%2,%3}, [%4];\n"
                 : "=r"(r[0]), "=r"(r[1]), "=r"(r[2]), "=r"(r[3]) : "r"(addr));
}
__device__ __forceinline__ void ldsm2(unsigned& r0, unsigned& r1, unsigned addr) {
    asm volatile("ldmatrix.sync.aligned.m8n8.x2.shared.b16 {%0,%1}, [%2];\n"
                 : "=r"(r0), "=r"(r1) : "r"(addr));
}
__device__ __forceinline__ void ldsm2t(unsigned& r0, unsigned& r1, unsigned addr) {
    asm volatile("ldmatrix.sync.aligned.m8n8.x2.trans.shared.b16 {%0,%1}, [%2];\n"
                 : "=r"(r0), "=r"(r1) : "r"(addr));
}

// ============== weights fp32 -> bf16, both matrices in one launch ==============
__global__ void wconv2(const float* __restrict__ wq, const float* __restrict__ wp) {
    int i = blockIdx.x * 256 + threadIdx.x;   // grid covers 262144 uint2
    const float* s; bf16* d; int j;
    if (i < 196608) { s = wq; d = g_wq; j = i; }
    else            { s = wp; d = g_wp; j = i - 196608; }
    float4 v = ((const float4*)s)[j];
    ((uint2*)d)[j] = pack4(v.x, v.y, v.z, v.w);
}

// ============================ GroupNorm (512 threads) ============================
__global__ void groupnorm_kernel(const float* __restrict__ x,
                                 const float* __restrict__ gamma,
                                 const float* __restrict__ beta) {
    extern __shared__ float4 sx[];
    int bg = blockIdx.x;
    int b = bg >> 5, g = bg & 31;
    size_t base = ((size_t)(b * C_ + g * 16)) * HW;
    const float4* xin = (const float4*)(x + base);

    float s = 0.f, s2 = 0.f;
    for (int q = threadIdx.x; q < 4096; q += 512) {
        float4 v = xin[q];
        sx[q] = v;
        s  += v.x + v.y + v.z + v.w;
        s2 += v.x * v.x + v.y * v.y + v.z * v.z + v.w * v.w;
    }
    __shared__ float red[2][16];
    #pragma unroll
    for (int o = 16; o; o >>= 1) {
        s  += __shfl_xor_sync(~0u, s, o);
        s2 += __shfl_xor_sync(~0u, s2, o);
    }
    int w = threadIdx.x >> 5, l = threadIdx.x & 31;
    if (l == 0) { red[0][w] = s; red[1][w] = s2; }
    __syncthreads();
    if (threadIdx.x == 0) {
        float ts = 0.f, ts2 = 0.f;
        #pragma unroll
        for (int i = 0; i < 16; i++) { ts += red[0][i]; ts2 += red[1][i]; }
        float mu  = ts / 16384.f;
        float var = ts2 / 16384.f - mu * mu;
        red[0][0] = mu;
        red[1][0] = rsqrtf(var + 1e-5f);
    }
    __syncthreads();
    float mu = red[0][0], rstd = red[1][0];
    uint2* outp = (uint2*)(g_h + base);
    for (int q = threadIdx.x; q < 4096; q += 512) {
        float4 v = sx[q];
        int c = g * 16 + (q >> 8);
        float ga = gamma[c] * rstd;
        float be = beta[c] - mu * ga;
        outp[q] = pack4(v.x * ga + be, v.y * ga + be, v.z * ga + be, v.w * ga + be);
    }
}

// =============== Raw-mma GEMM, 5-stage cp.async, register epilogue ==========
// out[b][o][p] = (res? x : 0) + bias[o] + sum_c w[o][c]*in[b][c][p]
// Block 128(o) x 128(p), BK=32; 8 warps as 4(m)x2(n), warp tile 32x64.
template <bool RES>
__global__ __launch_bounds__(256, 2)
void gemm_mma(const bf16* __restrict__ in, const bf16* __restrict__ w,
              const float* __restrict__ bias, const float* __restrict__ res,
              void* __restrict__ outv, int OC) {
    extern __shared__ char smc[];
    bf16* sA = (bf16*)smc;              // [5][128][40]
    bf16* sB = (bf16*)(smc + 51200);    // [5][32][136]

    int b = blockIdx.z;
    int o0 = blockIdx.y * 128, p0 = blockIdx.x * 128;
    int tid = threadIdx.x, wid = tid >> 5, lane = tid & 31;
    int wm = wid >> 1, wn = wid & 1;
    int l16 = lane & 15, lhi = lane >> 4;

    const bf16* wbase = w + (size_t)o0 * C_;
    const bf16* ibase = in + ((size_t)b * C_) * HW + p0;

    float acc[2][8][4] = {};

    auto issue = [&](int it) {
        if (it < 16) {
            int bu = it % 5, c0 = it * 32;
            bf16* dA = sA + bu * 5120;
            bf16* dB = sB + bu * 4352;
            #pragma unroll
            for (int u = 0; u < 2; u++) {
                int idx = tid + u * 256;
                int o = idx >> 2, kq = (idx & 3) * 8;
                cp16(dA + o * 40 + kq, wbase + (size_t)o * C_ + c0 + kq);
                int k = idx >> 4, jq = (idx & 15) * 8;
                cp16(dB + k * 136 + jq, ibase + (size_t)(c0 + k) * HW + jq);
            }
        }
        cp_commit();
    };

    issue(0); issue(1); issue(2); issue(3);
    unsigned abase = (unsigned)__cvta_generic_to_shared(sA);
    unsigned bbase = (unsigned)__cvta_generic_to_shared(sB);

    for (int it = 0; it < 16; it++) {
        cp_wait3();
        __syncthreads();
        issue(it + 4);
        unsigned A  = abase + (it % 5) * 10240;
        unsigned Bb = bbase + (it % 5) * 8704;
        #pragma unroll
        for (int kk = 0; kk < 2; kk++) {
            unsigned aq[2][4];
            #pragma unroll
            for (int mi = 0; mi < 2; mi++)
                ldsm4(aq[mi], A + ((wm * 32 + mi * 16 + l16) * 40 + kk * 16) * 2 + lhi * 16);
            #pragma unroll
            for (int dn2 = 0; dn2 < 4; dn2++) {
                unsigned bq[4];
                ldsm4t(bq, Bb + ((kk * 16 + l16) * 136 + wn * 64 + dn2 * 16) * 2 + lhi * 16);
                #pragma unroll
                for (int mi = 0; mi < 2; mi++) {
                    mma16816(acc[mi][2 * dn2],     aq[mi], bq[0], bq[1]);
                    mma16816(acc[mi][2 * dn2 + 1], aq[mi], bq[2], bq[3]);
                }
            }
        }
    }

    #pragma unroll
    for (int mi = 0; mi < 2; mi++) {
        int ro = o0 + wm * 32 + mi * 16 + (lane >> 2);
        float b0 = bias[ro], b1 = bias[ro + 8];
        size_t a0 = ((size_t)b * OC + ro) * HW + p0 + wn * 64 + (lane & 3) * 2;
        size_t a1 = a0 + 8 * HW;
        #pragma unroll
        for (int dn = 0; dn < 8; dn++) {
            size_t off = dn * 8;
            if (RES) {
                float* of = (float*)outv;
                float2 r0 = *(const float2*)&res[a0 + off];
                float2 r1 = *(const float2*)&res[a1 + off];
                float2 v0 = {acc[mi][dn][0] + b0 + r0.x, acc[mi][dn][1] + b0 + r0.y};
                float2 v1 = {acc[mi][dn][2] + b1 + r1.x, acc[mi][dn][3] + b1 + r1.y};
                *(float2*)&of[a0 + off] = v0;
                *(float2*)&of[a1 + off] = v1;
            } else {
                bf16* ob = (bf16*)outv;
                *(unsigned*)&ob[a0 + off] = packu(acc[mi][dn][0] + b0, acc[mi][dn][1] + b0);
                *(unsigned*)&ob[a1 + off] = packu(acc[mi][dn][2] + b1, acc[mi][dn][3] + b1);
            }
        }
    }
}

// ======================= Raw-mma FA2-style attention =======================
// Q pre-scaled by DH^-0.5 * log2(e): S is in log2 domain; exp = ex2.bf16x2.
__global__ __launch_bounds__(256, 2) void attn_mma() {
    extern __shared__ char smc[];
    bf16* sQ = (bf16*)smc;                    // [128][72]
    bf16* sK = (bf16*)(smc + 18432);          // [3][64][72]
    bf16* sV = (bf16*)(smc + 18432 + 27648);  // [3][64][72]

    int bh = blockIdx.y;
    int b = bh >> 3, nh = bh & 7;
    int i0 = blockIdx.x * 128;
    int tid = threadIdx.x, wid = tid >> 5, lane = tid & 31;

    const bf16* qptr = g_qkv + ((size_t)(b * OC_QKV + nh * DH)) * HW + i0;
    const bf16* kptr = g_qkv + ((size_t)(b * OC_QKV + C_ + nh * DH)) * HW;
    const bf16* vptr = g_qkv + ((size_t)(b * OC_QKV + 2 * C_ + nh * DH)) * HW;

    auto issueKV = [&](int it) {
        int bu = it % 3, j0 = it * 64;
        bf16* dK = sK + bu * 4608;
        bf16* dV = sV + bu * 4608;
        #pragma unroll
        for (int u = 0; u < 2; u++) {
            int idx = tid + u * 256;
            int d = idx >> 3, jq = (idx & 7) * 8;
            cp16(dK + d * 72 + jq, kptr + (size_t)d * HW + j0 + jq);
            cp16(dV + d * 72 + jq, vptr + (size_t)d * HW + j0 + jq);
        }
        cp_commit();
    };

    issueKV(0); issueKV(1);

    const float QSCALE = 0.125f * 1.4426950408889634f;
    for (int e = tid; e < 1024; e += 256) {
        int d = e >> 4, i8 = (e & 15) * 8;
        uint4 v = *(const uint4*)&qptr[(size_t)d * HW + i8];
        bf16 tmp[8]; *(uint4*)tmp = v;
        #pragma unroll
        for (int z = 0; z < 8; z++)
            sQ[(i8 + z) * 72 + d] = __float2bfloat16(__bfloat162float(tmp[z]) * QSCALE);
    }
    __syncthreads();

    unsigned aq[4][4];
    {
        unsigned qb = (unsigned)__cvta_generic_to_shared(sQ);
        unsigned rowaddr = qb + ((wid * 16 + (lane & 15)) * 72 + (lane >> 4) * 8) * 2;
        #pragma unroll
        for (int kk = 0; kk < 4; kk++) ldsm4(aq[kk], rowaddr + kk * 32);
    }

    float co[8][4] = {};
    float rs0 = 0.f, rs1 = 0.f;
    unsigned kb0 = (unsigned)__cvta_generic_to_shared(sK);
    unsigned vb0 = (unsigned)__cvta_generic_to_shared(sV);
    int l16 = lane & 15, lr8 = lane & 7, half8 = ((lane >> 3) & 1) * 8;

    for (int it = 0; it < 16; it++) {
        if (it < 15) cp_wait1(); else cp_wait0();
        __syncthreads();
        if (it + 2 < 16) issueKV(it + 2);
        unsigned kb = kb0 + (it % 3) * 9216;
        unsigned vb = vb0 + (it % 3) * 9216;

        // S = Q K^T (log2 domain)
        float cs[8][4] = {};
        #pragma unroll
        for (int kk = 0; kk < 4; kk++) {
            unsigned ka = kb + ((kk * 16 + l16) * 72) * 2;
            #pragma unroll
            for (int jn = 0; jn < 8; jn++) {
                unsigned b0x, b1x;
                ldsm2t(b0x, b1x, ka + jn * 16);
                mma16816(cs[jn], aq[kk], b0x, b1x);
            }
        }

        // P = 2^S via bf16x2 MUFU; rowsum from the SAME bf16 values fed to PV
        unsigned ap[4][4];
        #pragma unroll
        for (int t = 0; t < 4; t++) {
            ap[t][0] = ex2_bf16x2(packu(cs[2 * t][0],     cs[2 * t][1]));
            ap[t][1] = ex2_bf16x2(packu(cs[2 * t][2],     cs[2 * t][3]));
            ap[t][2] = ex2_bf16x2(packu(cs[2 * t + 1][0], cs[2 * t + 1][1]));
            ap[t][3] = ex2_bf16x2(packu(cs[2 * t + 1][2], cs[2 * t + 1][3]));
            float2 f0 = __bfloat1622float2(*(__nv_bfloat162*)&ap[t][0]);
            float2 f1 = __bfloat1622float2(*(__nv_bfloat162*)&ap[t][1]);
            float2 f2 = __bfloat1622float2(*(__nv_bfloat162*)&ap[t][2]);
            float2 f3 = __bfloat1622float2(*(__nv_bfloat162*)&ap[t][3]);
            rs0 += f0.x + f0.y + f2.x + f2.y;
            rs1 += f1.x + f1.y + f3.x + f3.y;
        }

        // O += P V
        #pragma unroll
        for (int t = 0; t < 4; t++) {
            unsigned va = vb + (lr8 * 72 + t * 16 + half8) * 2;
            #pragma unroll
            for (int dn = 0; dn < 8; dn++) {
                unsigned b0x, b1x;
                ldsm2(b0x, b1x, va + dn * 8 * 72 * 2);
                mma16816(co[dn], ap[t], b0x, b1x);
            }
        }
    }

    rs0 += __shfl_xor_sync(~0u, rs0, 1); rs0 += __shfl_xor_sync(~0u, rs0, 2);
    rs1 += __shfl_xor_sync(~0u, rs1, 1); rs1 += __shfl_xor_sync(~0u, rs1, 2);
    float inv0 = 1.f / rs0, inv1 = 1.f / rs1;

    // write O; torch-faithful reshape: c = nh*64 + (i>>4), p = (i&15)*64 + d
    int ir0 = i0 + wid * 16 + (lane >> 2);
    int ir1 = ir0 + 8;
    size_t a0 = ((size_t)(b * C_ + nh * 64 + (ir0 >> 4))) * HW + (ir0 & 15) * 64;
    size_t a1 = ((size_t)(b * C_ + nh * 64 + (ir1 >> 4))) * HW + (ir1 & 15) * 64;
    #pragma unroll
    for (int dn = 0; dn < 8; dn++) {
        int d = dn * 8 + (lane & 3) * 2;
        *(unsigned*)&g_att[a0 + d] = packu(co[dn][0] * inv0, co[dn][1] * inv0);
        *(unsigned*)&g_att[a1 + d] = packu(co[dn][2] * inv1, co[dn][3] * inv1);
    }
}

// ============================ launch ============================
extern "C" void kernel_launch(void* const* d_in, const int* in_sizes, int n_in,
                              void* d_out, int out_size) {
    const float* x      = (const float*)d_in[0];
    const float* gamma  = (const float*)d_in[1];
    const float* beta   = (const float*)d_in[2];
    const float* qkv_w  = (const float*)d_in[3];
    const float* qkv_b  = (const float*)d_in[4];
    const float* proj_w = (const float*)d_in[5];
    const float* proj_b = (const float*)d_in[6];
    float* out = (float*)d_out;

    void *p_h, *p_qkv, *p_att, *p_wq, *p_wp;
    cudaGetSymbolAddress(&p_h, g_h);
    cudaGetSymbolAddress(&p_qkv, g_qkv);
    cudaGetSymbolAddress(&p_att, g_att);
    cudaGetSymbolAddress(&p_wq, g_wq);
    cudaGetSymbolAddress(&p_wp, g_wp);

    const int GEMM_SMEM = 94720;               // 5*(10240 + 8704)
    const int ATTN_SMEM = 18432 + 2 * 27648;   // 73728
    const int GN_SMEM   = 65536;
    cudaFuncSetAttribute(gemm_mma<false>,
                         cudaFuncAttributeMaxDynamicSharedMemorySize, GEMM_SMEM);
    cudaFuncSetAttribute(gemm_mma<true>,
                         cudaFuncAttributeMaxDynamicSharedMemorySize, GEMM_SMEM);
    cudaFuncSetAttribute(attn_mma,
                         cudaFuncAttributeMaxDynamicSharedMemorySize, ATTN_SMEM);
    cudaFuncSetAttribute(groupnorm_kernel,
                         cudaFuncAttributeMaxDynamicSharedMemorySize, GN_SMEM);

    wconv2<<<1024, 256>>>(qkv_w, proj_w);

    groupnorm_kernel<<<256, 512, GN_SMEM>>>(x, gamma, beta);

    gemm_mma<false><<<dim3(8, 12, B_), 256, GEMM_SMEM>>>(
        (const bf16*)p_h, (const bf16*)p_wq, qkv_b, nullptr, p_qkv, OC_QKV);

    attn_mma<<<dim3(8, 64), 256, ATTN_SMEM>>>();

    gemm_mma<true><<<dim3(8, 4, B_), 256, GEMM_SMEM>>>(
        (const bf16*)p_att, (const bf16*)p_wp, proj_b, x, out, C_);
}

// round 9
// speedup vs baseline: 7.2136x; 1.0297x over previous
#include <cuda_runtime.h>
#include <cuda_bf16.h>

#define B_ 8
#define C_ 512
#define HW 1024
#define NH 8
#define DH 64
#define OC_QKV 1536

typedef __nv_bfloat16 bf16;

// -------- scratch (static device globals; no allocation) --------
__device__ bf16 g_h[B_ * C_ * HW];
__device__ bf16 g_qkv[B_ * OC_QKV * HW];
__device__ bf16 g_att[B_ * C_ * HW];
__device__ bf16 g_wq[OC_QKV * C_];
__device__ bf16 g_wp[C_ * C_];

// -------- helpers --------
__device__ __forceinline__ void cp16(void* dst, const void* src) {
    unsigned d = (unsigned)__cvta_generic_to_shared(dst);
    asm volatile("cp.async.cg.shared.global [%0], [%1], 16;\n" :: "r"(d), "l"(src));
}
__device__ __forceinline__ void cp_commit() { asm volatile("cp.async.commit_group;\n" ::); }
__device__ __forceinline__ void cp_wait0()  { asm volatile("cp.async.wait_group 0;\n" ::); }
__device__ __forceinline__ void cp_wait1()  { asm volatile("cp.async.wait_group 1;\n" ::); }
__device__ __forceinline__ void cp_wait3()  { asm volatile("cp.async.wait_group 3;\n" ::); }

__device__ __forceinline__ uint2 pack4(float a, float b, float c, float d) {
    __nv_bfloat162 lo = __floats2bfloat162_rn(a, b);
    __nv_bfloat162 hi = __floats2bfloat162_rn(c, d);
    uint2 r; r.x = *(unsigned*)&lo; r.y = *(unsigned*)&hi; return r;
}
__device__ __forceinline__ unsigned packu(float a, float b) {
    __nv_bfloat162 t = __floats2bfloat162_rn(a, b);
    return *(unsigned*)&t;
}
__device__ __forceinline__ unsigned ex2_bf16x2(unsigned y) {
    unsigned r;
    asm("ex2.approx.ftz.bf16x2 %0, %1;" : "=r"(r) : "r"(y));
    return r;
}
__device__ __forceinline__ void mma16816(float* c, const unsigned* a, unsigned b0, unsigned b1) {
    asm volatile("mma.sync.aligned.m16n8k16.row.col.f32.bf16.bf16.f32 "
                 "{%0,%1,%2,%3}, {%4,%5,%6,%7}, {%8,%9}, {%0,%1,%2,%3};\n"
                 : "+f"(c[0]), "+f"(c[1]), "+f"(c[2]), "+f"(c[3])
                 : "r"(a[0]), "r"(a[1]), "r"(a[2]), "r"(a[3]), "r"(b0), "r"(b1));
}
__device__ __forceinline__ void ldsm4(unsigned* r, unsigned addr) {
    asm volatile("ldmatrix.sync.aligned.m8n8.x4.shared.b16 {%0,%1,%2,%3}, [%4];\n"
                 : "=r"(r[0]), "=r"(r[1]), "=r"(r[2]), "=r"(r[3]) : "r"(addr));
}
__device__ __forceinline__ void ldsm4t(unsigned* r, unsigned addr) {
    asm volatile("ldmatrix.sync.aligned.m8n8.x4.trans.shared.b16 {%0,%1,%2,%3}, [%4];\n"
                 : "=r"(r[0]), "=r"(r[1]), "=r"(r[2]), "=r"(r[3]) : "r"(addr));
}

// ============== weights fp32 -> bf16, both matrices in one launch ==============
__global__ void wconv2(const float* __restrict__ wq, const float* __restrict__ wp) {
    int i = blockIdx.x * 256 + threadIdx.x;
    const float* s; bf16* d; int j;
    if (i < 196608) { s = wq; d = g_wq; j = i; }
    else            { s = wp; d = g_wp; j = i - 196608; }
    float4 v = ((const float4*)s)[j];
    ((uint2*)d)[j] = pack4(v.x, v.y, v.z, v.w);
}

// ============================ GroupNorm (512 threads) ============================
__global__ void groupnorm_kernel(const float* __restrict__ x,
                                 const float* __restrict__ gamma,
                                 const float* __restrict__ beta) {
    extern __shared__ float4 sx[];
    int bg = blockIdx.x;
    int b = bg >> 5, g = bg & 31;
    size_t base = ((size_t)(b * C_ + g * 16)) * HW;
    const float4* xin = (const float4*)(x + base);

    float s = 0.f, s2 = 0.f;
    for (int q = threadIdx.x; q < 4096; q += 512) {
        float4 v = xin[q];
        sx[q] = v;
        s  += v.x + v.y + v.z + v.w;
        s2 += v.x * v.x + v.y * v.y + v.z * v.z + v.w * v.w;
    }
    __shared__ float red[2][16];
    #pragma unroll
    for (int o = 16; o; o >>= 1) {
        s  += __shfl_xor_sync(~0u, s, o);
        s2 += __shfl_xor_sync(~0u, s2, o);
    }
    int w = threadIdx.x >> 5, l = threadIdx.x & 31;
    if (l == 0) { red[0][w] = s; red[1][w] = s2; }
    __syncthreads();
    if (threadIdx.x == 0) {
        float ts = 0.f, ts2 = 0.f;
        #pragma unroll
        for (int i = 0; i < 16; i++) { ts += red[0][i]; ts2 += red[1][i]; }
        float mu  = ts / 16384.f;
        float var = ts2 / 16384.f - mu * mu;
        red[0][0] = mu;
        red[1][0] = rsqrtf(var + 1e-5f);
    }
    __syncthreads();
    float mu = red[0][0], rstd = red[1][0];
    uint2* outp = (uint2*)(g_h + base);
    for (int q = threadIdx.x; q < 4096; q += 512) {
        float4 v = sx[q];
        int c = g * 16 + (q >> 8);
        float ga = gamma[c] * rstd;
        float be = beta[c] - mu * ga;
        outp[q] = pack4(v.x * ga + be, v.y * ga + be, v.z * ga + be, v.w * ga + be);
    }
}

// =============== Raw-mma GEMM, 5-stage cp.async, register epilogue ==========
template <bool RES>
__global__ __launch_bounds__(256, 2)
void gemm_mma(const bf16* __restrict__ in, const bf16* __restrict__ w,
              const float* __restrict__ bias, const float* __restrict__ res,
              void* __restrict__ outv, int OC) {
    extern __shared__ char smc[];
    bf16* sA = (bf16*)smc;              // [5][128][40]
    bf16* sB = (bf16*)(smc + 51200);    // [5][32][136]

    int b = blockIdx.z;
    int o0 = blockIdx.y * 128, p0 = blockIdx.x * 128;
    int tid = threadIdx.x, wid = tid >> 5, lane = tid & 31;
    int wm = wid >> 1, wn = wid & 1;
    int l16 = lane & 15, lhi = lane >> 4;

    const bf16* wbase = w + (size_t)o0 * C_;
    const bf16* ibase = in + ((size_t)b * C_) * HW + p0;

    float acc[2][8][4] = {};

    auto issue = [&](int it) {
        if (it < 16) {
            int bu = it % 5, c0 = it * 32;
            bf16* dA = sA + bu * 5120;
            bf16* dB = sB + bu * 4352;
            #pragma unroll
            for (int u = 0; u < 2; u++) {
                int idx = tid + u * 256;
                int o = idx >> 2, kq = (idx & 3) * 8;
                cp16(dA + o * 40 + kq, wbase + (size_t)o * C_ + c0 + kq);
                int k = idx >> 4, jq = (idx & 15) * 8;
                cp16(dB + k * 136 + jq, ibase + (size_t)(c0 + k) * HW + jq);
            }
        }
        cp_commit();
    };

    issue(0); issue(1); issue(2); issue(3);
    unsigned abase = (unsigned)__cvta_generic_to_shared(sA);
    unsigned bbase = (unsigned)__cvta_generic_to_shared(sB);

    for (int it = 0; it < 16; it++) {
        cp_wait3();
        __syncthreads();
        issue(it + 4);
        unsigned A  = abase + (it % 5) * 10240;
        unsigned Bb = bbase + (it % 5) * 8704;
        #pragma unroll
        for (int kk = 0; kk < 2; kk++) {
            unsigned aq[2][4];
            #pragma unroll
            for (int mi = 0; mi < 2; mi++)
                ldsm4(aq[mi], A + ((wm * 32 + mi * 16 + l16) * 40 + kk * 16) * 2 + lhi * 16);
            #pragma unroll
            for (int dn2 = 0; dn2 < 4; dn2++) {
                unsigned bq[4];
                ldsm4t(bq, Bb + ((kk * 16 + l16) * 136 + wn * 64 + dn2 * 16) * 2 + lhi * 16);
                #pragma unroll
                for (int mi = 0; mi < 2; mi++) {
                    mma16816(acc[mi][2 * dn2],     aq[mi], bq[0], bq[1]);
                    mma16816(acc[mi][2 * dn2 + 1], aq[mi], bq[2], bq[3]);
                }
            }
        }
    }

    #pragma unroll
    for (int mi = 0; mi < 2; mi++) {
        int ro = o0 + wm * 32 + mi * 16 + (lane >> 2);
        float b0 = bias[ro], b1 = bias[ro + 8];
        size_t a0 = ((size_t)b * OC + ro) * HW + p0 + wn * 64 + (lane & 3) * 2;
        size_t a1 = a0 + 8 * HW;
        #pragma unroll
        for (int dn = 0; dn < 8; dn++) {
            size_t off = dn * 8;
            if (RES) {
                float* of = (float*)outv;
                float2 r0 = *(const float2*)&res[a0 + off];
                float2 r1 = *(const float2*)&res[a1 + off];
                float2 v0 = {acc[mi][dn][0] + b0 + r0.x, acc[mi][dn][1] + b0 + r0.y};
                float2 v1 = {acc[mi][dn][2] + b1 + r1.x, acc[mi][dn][3] + b1 + r1.y};
                *(float2*)&of[a0 + off] = v0;
                *(float2*)&of[a1 + off] = v1;
            } else {
                bf16* ob = (bf16*)outv;
                *(unsigned*)&ob[a0 + off] = packu(acc[mi][dn][0] + b0, acc[mi][dn][1] + b0);
                *(unsigned*)&ob[a1 + off] = packu(acc[mi][dn][2] + b1, acc[mi][dn][3] + b1);
            }
        }
    }
}

// ======================= Raw-mma FA2-style attention =======================
// Q pre-scaled by DH^-0.5 * log2(e): S in log2 domain; exp = ex2.bf16x2.
// x4 ldmatrix (two n-groups per load); rowsum via ones-column HMMA.
__global__ __launch_bounds__(256, 2) void attn_mma() {
    extern __shared__ char smc[];
    bf16* sQ = (bf16*)smc;                    // [128][72]
    bf16* sK = (bf16*)(smc + 18432);          // [3][64][72]
    bf16* sV = (bf16*)(smc + 18432 + 27648);  // [3][64][72]

    int bh = blockIdx.y;
    int b = bh >> 3, nh = bh & 7;
    int i0 = blockIdx.x * 128;
    int tid = threadIdx.x, wid = tid >> 5, lane = tid & 31;

    const bf16* qptr = g_qkv + ((size_t)(b * OC_QKV + nh * DH)) * HW + i0;
    const bf16* kptr = g_qkv + ((size_t)(b * OC_QKV + C_ + nh * DH)) * HW;
    const bf16* vptr = g_qkv + ((size_t)(b * OC_QKV + 2 * C_ + nh * DH)) * HW;

    auto issueKV = [&](int it) {
        int bu = it % 3, j0 = it * 64;
        bf16* dK = sK + bu * 4608;
        bf16* dV = sV + bu * 4608;
        #pragma unroll
        for (int u = 0; u < 2; u++) {
            int idx = tid + u * 256;
            int d = idx >> 3, jq = (idx & 7) * 8;
            cp16(dK + d * 72 + jq, kptr + (size_t)d * HW + j0 + jq);
            cp16(dV + d * 72 + jq, vptr + (size_t)d * HW + j0 + jq);
        }
        cp_commit();
    };

    issueKV(0); issueKV(1);

    const float QSCALE = 0.125f * 1.4426950408889634f;
    for (int e = tid; e < 1024; e += 256) {
        int d = e >> 4, i8 = (e & 15) * 8;
        uint4 v = *(const uint4*)&qptr[(size_t)d * HW + i8];
        bf16 tmp[8]; *(uint4*)tmp = v;
        #pragma unroll
        for (int z = 0; z < 8; z++)
            sQ[(i8 + z) * 72 + d] = __float2bfloat16(__bfloat162float(tmp[z]) * QSCALE);
    }
    __syncthreads();

    unsigned aq[4][4];
    {
        unsigned qb = (unsigned)__cvta_generic_to_shared(sQ);
        unsigned rowaddr = qb + ((wid * 16 + (lane & 15)) * 72 + (lane >> 4) * 8) * 2;
        #pragma unroll
        for (int kk = 0; kk < 4; kk++) ldsm4(aq[kk], rowaddr + kk * 32);
    }

    float co[8][4] = {};
    float crow[4] = {};     // rowsum accumulator: C[:,0] = P @ ones
    unsigned kb0 = (unsigned)__cvta_generic_to_shared(sK);
    unsigned vb0 = (unsigned)__cvta_generic_to_shared(sV);
    int l16 = lane & 15, lr8 = lane & 7, half8 = ((lane >> 3) & 1) * 8;
    int joff16 = (lane >> 4) * 16;              // K x4: lanes 16-31 -> next j-group
    int doff   = (lane >> 4) * (8 * 72 * 2);    // V x4: lanes 16-31 -> next d-group
    // B-frag of ones-column matrix (B[k][0]=1): constant per lane
    unsigned ones_b = (lane < 4) ? 0x3F803F80u : 0u;

    for (int it = 0; it < 16; it++) {
        if (it < 15) cp_wait1(); else cp_wait0();
        __syncthreads();
        if (it + 2 < 16) issueKV(it + 2);
        unsigned kb = kb0 + (it % 3) * 9216;
        unsigned vb = vb0 + (it % 3) * 9216;

        // S = Q K^T (log2 domain): 16 ldsm4t, 32 mma
        float cs[8][4] = {};
        #pragma unroll
        for (int kk = 0; kk < 4; kk++) {
            unsigned ka = kb + ((kk * 16 + l16) * 72) * 2 + joff16;
            #pragma unroll
            for (int jn = 0; jn < 8; jn += 2) {
                unsigned r[4];
                ldsm4t(r, ka + jn * 16);
                mma16816(cs[jn],     aq[kk], r[0], r[1]);
                mma16816(cs[jn + 1], aq[kk], r[2], r[3]);
            }
        }

        // P = 2^S via bf16x2 MUFU
        unsigned ap[4][4];
        #pragma unroll
        for (int t = 0; t < 4; t++) {
            ap[t][0] = ex2_bf16x2(packu(cs[2 * t][0],     cs[2 * t][1]));
            ap[t][1] = ex2_bf16x2(packu(cs[2 * t][2],     cs[2 * t][3]));
            ap[t][2] = ex2_bf16x2(packu(cs[2 * t + 1][0], cs[2 * t + 1][1]));
            ap[t][3] = ex2_bf16x2(packu(cs[2 * t + 1][2], cs[2 * t + 1][3]));
        }

        // rowsum += P @ ones  (4 HMMA; replaces 64 cvt/add ops)
        #pragma unroll
        for (int t = 0; t < 4; t++)
            mma16816(crow, ap[t], ones_b, ones_b);

        // O += P V: 16 ldsm4, 32 mma
        #pragma unroll
        for (int t = 0; t < 4; t++) {
            unsigned va = vb + (lr8 * 72 + t * 16 + half8) * 2 + doff;
            #pragma unroll
            for (int dn = 0; dn < 8; dn += 2) {
                unsigned r[4];
                ldsm4(r, va + dn * 8 * 72 * 2);
                mma16816(co[dn],     ap[t], r[0], r[1]);
                mma16816(co[dn + 1], ap[t], r[2], r[3]);
            }
        }
    }

    // rowsum lives in lanes with (lane&3)==0: crow[0]=row r, crow[2]=row r+8
    float inv0 = 1.f / __shfl_sync(~0u, crow[0], lane & 28);
    float inv1 = 1.f / __shfl_sync(~0u, crow[2], lane & 28);

    // write O; torch-faithful reshape: c = nh*64 + (i>>4), p = (i&15)*64 + d
    int ir0 = i0 + wid * 16 + (lane >> 2);
    int ir1 = ir0 + 8;
    size_t a0 = ((size_t)(b * C_ + nh * 64 + (ir0 >> 4))) * HW + (ir0 & 15) * 64;
    size_t a1 = ((size_t)(b * C_ + nh * 64 + (ir1 >> 4))) * HW + (ir1 & 15) * 64;
    #pragma unroll
    for (int dn = 0; dn < 8; dn++) {
        int d = dn * 8 + (lane & 3) * 2;
        *(unsigned*)&g_att[a0 + d] = packu(co[dn][0] * inv0, co[dn][1] * inv0);
        *(unsigned*)&g_att[a1 + d] = packu(co[dn][2] * inv1, co[dn][3] * inv1);
    }
}

// ============================ launch ============================
extern "C" void kernel_launch(void* const* d_in, const int* in_sizes, int n_in,
                              void* d_out, int out_size) {
    const float* x      = (const float*)d_in[0];
    const float* gamma  = (const float*)d_in[1];
    const float* beta   = (const float*)d_in[2];
    const float* qkv_w  = (const float*)d_in[3];
    const float* qkv_b  = (const float*)d_in[4];
    const float* proj_w = (const float*)d_in[5];
    const float* proj_b = (const float*)d_in[6];
    float* out = (float*)d_out;

    void *p_h, *p_qkv, *p_att, *p_wq, *p_wp;
    cudaGetSymbolAddress(&p_h, g_h);
    cudaGetSymbolAddress(&p_qkv, g_qkv);
    cudaGetSymbolAddress(&p_att, g_att);
    cudaGetSymbolAddress(&p_wq, g_wq);
    cudaGetSymbolAddress(&p_wp, g_wp);

    const int GEMM_SMEM = 94720;
    const int ATTN_SMEM = 18432 + 2 * 27648;
    const int GN_SMEM   = 65536;
    cudaFuncSetAttribute(gemm_mma<false>,
                         cudaFuncAttributeMaxDynamicSharedMemorySize, GEMM_SMEM);
    cudaFuncSetAttribute(gemm_mma<true>,
                         cudaFuncAttributeMaxDynamicSharedMemorySize, GEMM_SMEM);
    cudaFuncSetAttribute(attn_mma,
                         cudaFuncAttributeMaxDynamicSharedMemorySize, ATTN_SMEM);
    cudaFuncSetAttribute(groupnorm_kernel,
                         cudaFuncAttributeMaxDynamicSharedMemorySize, GN_SMEM);

    wconv2<<<1024, 256>>>(qkv_w, proj_w);

    groupnorm_kernel<<<256, 512, GN_SMEM>>>(x, gamma, beta);

    gemm_mma<false><<<dim3(8, 12, B_), 256, GEMM_SMEM>>>(
        (const bf16*)p_h, (const bf16*)p_wq, qkv_b, nullptr, p_qkv, OC_QKV);

    attn_mma<<<dim3(8, 64), 256, ATTN_SMEM>>>();

    gemm_mma<true><<<dim3(8, 4, B_), 256, GEMM_SMEM>>>(
        (const bf16*)p_att, (const bf16*)p_wp, proj_b, x, out, C_);
}

// round 10
// speedup vs baseline: 7.3208x; 1.0149x over previous
#include <cuda_runtime.h>
#include <cuda_bf16.h>

#define B_ 8
#define C_ 512
#define HW 1024
#define NH 8
#define DH 64
#define OC_QKV 1536

typedef __nv_bfloat16 bf16;

// -------- scratch (static device globals; no allocation) --------
__device__ bf16 g_h[B_ * C_ * HW];
__device__ bf16 g_qkv[B_ * OC_QKV * HW];
__device__ bf16 g_att[B_ * C_ * HW];
__device__ bf16 g_wq[OC_QKV * C_];
__device__ bf16 g_wp[C_ * C_];

// -------- helpers --------
__device__ __forceinline__ void cp16(void* dst, const void* src) {
    unsigned d = (unsigned)__cvta_generic_to_shared(dst);
    asm volatile("cp.async.cg.shared.global [%0], [%1], 16;\n" :: "r"(d), "l"(src));
}
__device__ __forceinline__ void cp_commit() { asm volatile("cp.async.commit_group;\n" ::); }
__device__ __forceinline__ void cp_wait0()  { asm volatile("cp.async.wait_group 0;\n" ::); }
__device__ __forceinline__ void cp_wait1()  { asm volatile("cp.async.wait_group 1;\n" ::); }
__device__ __forceinline__ void cp_wait3()  { asm volatile("cp.async.wait_group 3;\n" ::); }

__device__ __forceinline__ uint2 pack4(float a, float b, float c, float d) {
    __nv_bfloat162 lo = __floats2bfloat162_rn(a, b);
    __nv_bfloat162 hi = __floats2bfloat162_rn(c, d);
    uint2 r; r.x = *(unsigned*)&lo; r.y = *(unsigned*)&hi; return r;
}
__device__ __forceinline__ unsigned packu(float a, float b) {
    __nv_bfloat162 t = __floats2bfloat162_rn(a, b);
    return *(unsigned*)&t;
}
__device__ __forceinline__ unsigned ex2_bf16x2(unsigned y) {
    unsigned r;
    asm("ex2.approx.ftz.bf16x2 %0, %1;" : "=r"(r) : "r"(y));
    return r;
}
__device__ __forceinline__ void mma16816(float* c, const unsigned* a, unsigned b0, unsigned b1) {
    asm volatile("mma.sync.aligned.m16n8k16.row.col.f32.bf16.bf16.f32 "
                 "{%0,%1,%2,%3}, {%4,%5,%6,%7}, {%8,%9}, {%0,%1,%2,%3};\n"
                 : "+f"(c[0]), "+f"(c[1]), "+f"(c[2]), "+f"(c[3])
                 : "r"(a[0]), "r"(a[1]), "r"(a[2]), "r"(a[3]), "r"(b0), "r"(b1));
}
__device__ __forceinline__ void ldsm4(unsigned* r, unsigned addr) {
    asm volatile("ldmatrix.sync.aligned.m8n8.x4.shared.b16 {%0,%1,%2,%3}, [%4];\n"
                 : "=r"(r[0]), "=r"(r[1]), "=r"(r[2]), "=r"(r[3]) : "r"(addr));
}
__device__ __forceinline__ void ldsm4t(unsigned* r, unsigned addr) {
    asm volatile("ldmatrix.sync.aligned.m8n8.x4.trans.shared.b16 {%0,%1,%2,%3}, [%4];\n"
                 : "=r"(r[0]), "=r"(r[1]), "=r"(r[2]), "=r"(r[3]) : "r"(addr));
}

// ============== weights fp32 -> bf16, both matrices in one launch ==============
__global__ void wconv2(const float* __restrict__ wq, const float* __restrict__ wp) {
    int i = blockIdx.x * 256 + threadIdx.x;
    const float* s; bf16* d; int j;
    if (i < 196608) { s = wq; d = g_wq; j = i; }
    else            { s = wp; d = g_wp; j = i - 196608; }
    float4 v = ((const float4*)s)[j];
    ((uint2*)d)[j] = pack4(v.x, v.y, v.z, v.w);
}

// ============================ GroupNorm (512 threads) ============================
__global__ void groupnorm_kernel(const float* __restrict__ x,
                                 const float* __restrict__ gamma,
                                 const float* __restrict__ beta) {
    extern __shared__ float4 sx[];
    int bg = blockIdx.x;
    int b = bg >> 5, g = bg & 31;
    size_t base = ((size_t)(b * C_ + g * 16)) * HW;
    const float4* xin = (const float4*)(x + base);

    float s = 0.f, s2 = 0.f;
    for (int q = threadIdx.x; q < 4096; q += 512) {
        float4 v = xin[q];
        sx[q] = v;
        s  += v.x + v.y + v.z + v.w;
        s2 += v.x * v.x + v.y * v.y + v.z * v.z + v.w * v.w;
    }
    __shared__ float red[2][16];
    #pragma unroll
    for (int o = 16; o; o >>= 1) {
        s  += __shfl_xor_sync(~0u, s, o);
        s2 += __shfl_xor_sync(~0u, s2, o);
    }
    int w = threadIdx.x >> 5, l = threadIdx.x & 31;
    if (l == 0) { red[0][w] = s; red[1][w] = s2; }
    __syncthreads();
    if (threadIdx.x == 0) {
        float ts = 0.f, ts2 = 0.f;
        #pragma unroll
        for (int i = 0; i < 16; i++) { ts += red[0][i]; ts2 += red[1][i]; }
        float mu  = ts / 16384.f;
        float var = ts2 / 16384.f - mu * mu;
        red[0][0] = mu;
        red[1][0] = rsqrtf(var + 1e-5f);
    }
    __syncthreads();
    float mu = red[0][0], rstd = red[1][0];
    uint2* outp = (uint2*)(g_h + base);
    for (int q = threadIdx.x; q < 4096; q += 512) {
        float4 v = sx[q];
        int c = g * 16 + (q >> 8);
        float ga = gamma[c] * rstd;
        float be = beta[c] - mu * ga;
        outp[q] = pack4(v.x * ga + be, v.y * ga + be, v.z * ga + be, v.w * ga + be);
    }
}

// =============== Raw-mma GEMM, 5-stage cp.async, register epilogue ==========
template <bool RES>
__global__ __launch_bounds__(256, 2)
void gemm_mma(const bf16* __restrict__ in, const bf16* __restrict__ w,
              const float* __restrict__ bias, const float* __restrict__ res,
              void* __restrict__ outv, int OC) {
    extern __shared__ char smc[];
    bf16* sA = (bf16*)smc;              // [5][128][40]
    bf16* sB = (bf16*)(smc + 51200);    // [5][32][136]

    int b = blockIdx.z;
    int o0 = blockIdx.y * 128, p0 = blockIdx.x * 128;
    int tid = threadIdx.x, wid = tid >> 5, lane = tid & 31;
    int wm = wid >> 1, wn = wid & 1;
    int l16 = lane & 15, lhi = lane >> 4;

    const bf16* wbase = w + (size_t)o0 * C_;
    const bf16* ibase = in + ((size_t)b * C_) * HW + p0;

    float acc[2][8][4] = {};

    auto issue = [&](int it) {
        if (it < 16) {
            int bu = it % 5, c0 = it * 32;
            bf16* dA = sA + bu * 5120;
            bf16* dB = sB + bu * 4352;
            #pragma unroll
            for (int u = 0; u < 2; u++) {
                int idx = tid + u * 256;
                int o = idx >> 2, kq = (idx & 3) * 8;
                cp16(dA + o * 40 + kq, wbase + (size_t)o * C_ + c0 + kq);
                int k = idx >> 4, jq = (idx & 15) * 8;
                cp16(dB + k * 136 + jq, ibase + (size_t)(c0 + k) * HW + jq);
            }
        }
        cp_commit();
    };

    issue(0); issue(1); issue(2); issue(3);
    unsigned abase = (unsigned)__cvta_generic_to_shared(sA);
    unsigned bbase = (unsigned)__cvta_generic_to_shared(sB);

    for (int it = 0; it < 16; it++) {
        cp_wait3();
        __syncthreads();
        issue(it + 4);
        unsigned A  = abase + (it % 5) * 10240;
        unsigned Bb = bbase + (it % 5) * 8704;
        #pragma unroll
        for (int kk = 0; kk < 2; kk++) {
            unsigned aq[2][4];
            #pragma unroll
            for (int mi = 0; mi < 2; mi++)
                ldsm4(aq[mi], A + ((wm * 32 + mi * 16 + l16) * 40 + kk * 16) * 2 + lhi * 16);
            #pragma unroll
            for (int dn2 = 0; dn2 < 4; dn2++) {
                unsigned bq[4];
                ldsm4t(bq, Bb + ((kk * 16 + l16) * 136 + wn * 64 + dn2 * 16) * 2 + lhi * 16);
                #pragma unroll
                for (int mi = 0; mi < 2; mi++) {
                    mma16816(acc[mi][2 * dn2],     aq[mi], bq[0], bq[1]);
                    mma16816(acc[mi][2 * dn2 + 1], aq[mi], bq[2], bq[3]);
                }
            }
        }
    }

    #pragma unroll
    for (int mi = 0; mi < 2; mi++) {
        int ro = o0 + wm * 32 + mi * 16 + (lane >> 2);
        float b0 = bias[ro], b1 = bias[ro + 8];
        size_t a0 = ((size_t)b * OC + ro) * HW + p0 + wn * 64 + (lane & 3) * 2;
        size_t a1 = a0 + 8 * HW;
        #pragma unroll
        for (int dn = 0; dn < 8; dn++) {
            size_t off = dn * 8;
            if (RES) {
                float* of = (float*)outv;
                float2 r0 = *(const float2*)&res[a0 + off];
                float2 r1 = *(const float2*)&res[a1 + off];
                float2 v0 = {acc[mi][dn][0] + b0 + r0.x, acc[mi][dn][1] + b0 + r0.y};
                float2 v1 = {acc[mi][dn][2] + b1 + r1.x, acc[mi][dn][3] + b1 + r1.y};
                *(float2*)&of[a0 + off] = v0;
                *(float2*)&of[a1 + off] = v1;
            } else {
                bf16* ob = (bf16*)outv;
                *(unsigned*)&ob[a0 + off] = packu(acc[mi][dn][0] + b0, acc[mi][dn][1] + b0);
                *(unsigned*)&ob[a1 + off] = packu(acc[mi][dn][2] + b1, acc[mi][dn][3] + b1);
            }
        }
    }
}

// ======================= Raw-mma FA2-style attention =======================
// 4 warps, 128 threads; warp owns 32 Q rows (2 m-groups) -> K/V smem reads
// amortized over 2x MMAs. Q pre-scaled by DH^-0.5*log2(e); exp = ex2.bf16x2;
// rowsum via ones-column HMMA.
__global__ __launch_bounds__(128, 2) void attn_mma() {
    extern __shared__ char smc[];
    bf16* sQ = (bf16*)smc;                    // [128][72]
    bf16* sK = (bf16*)(smc + 18432);          // [3][64][72]
    bf16* sV = (bf16*)(smc + 18432 + 27648);  // [3][64][72]

    int bh = blockIdx.y;
    int b = bh >> 3, nh = bh & 7;
    int i0 = blockIdx.x * 128;
    int tid = threadIdx.x, wid = tid >> 5, lane = tid & 31;

    const bf16* qptr = g_qkv + ((size_t)(b * OC_QKV + nh * DH)) * HW + i0;
    const bf16* kptr = g_qkv + ((size_t)(b * OC_QKV + C_ + nh * DH)) * HW;
    const bf16* vptr = g_qkv + ((size_t)(b * OC_QKV + 2 * C_ + nh * DH)) * HW;

    auto issueKV = [&](int it) {
        int bu = it % 3, j0 = it * 64;
        bf16* dK = sK + bu * 4608;
        bf16* dV = sV + bu * 4608;
        #pragma unroll
        for (int u = 0; u < 4; u++) {
            int idx = tid + u * 128;
            int d = idx >> 3, jq = (idx & 7) * 8;
            cp16(dK + d * 72 + jq, kptr + (size_t)d * HW + j0 + jq);
            cp16(dV + d * 72 + jq, vptr + (size_t)d * HW + j0 + jq);
        }
        cp_commit();
    };

    issueKV(0); issueKV(1);

    const float QSCALE = 0.125f * 1.4426950408889634f;
    for (int e = tid; e < 1024; e += 128) {
        int d = e >> 4, i8 = (e & 15) * 8;
        uint4 v = *(const uint4*)&qptr[(size_t)d * HW + i8];
        bf16 tmp[8]; *(uint4*)tmp = v;
        #pragma unroll
        for (int z = 0; z < 8; z++)
            sQ[(i8 + z) * 72 + d] = __float2bfloat16(__bfloat162float(tmp[z]) * QSCALE);
    }
    __syncthreads();

    // Q fragments for 2 m-groups x 4 k-steps
    unsigned aq[2][4][4];
    {
        unsigned qb = (unsigned)__cvta_generic_to_shared(sQ);
        #pragma unroll
        for (int mi = 0; mi < 2; mi++) {
            unsigned rowaddr = qb +
                ((wid * 32 + mi * 16 + (lane & 15)) * 72 + (lane >> 4) * 8) * 2;
            #pragma unroll
            for (int kk = 0; kk < 4; kk++) ldsm4(aq[mi][kk], rowaddr + kk * 32);
        }
    }

    float co[2][8][4] = {};
    float crow[2][4] = {};
    unsigned kb0 = (unsigned)__cvta_generic_to_shared(sK);
    unsigned vb0 = (unsigned)__cvta_generic_to_shared(sV);
    int l16 = lane & 15, lr8 = lane & 7, half8 = ((lane >> 3) & 1) * 8;
    int joff16 = (lane >> 4) * 16;
    int doff   = (lane >> 4) * (8 * 72 * 2);
    unsigned ones_b = (lane < 4) ? 0x3F803F80u : 0u;

    for (int it = 0; it < 16; it++) {
        if (it < 15) cp_wait1(); else cp_wait0();
        __syncthreads();
        if (it + 2 < 16) issueKV(it + 2);
        unsigned kb = kb0 + (it % 3) * 9216;
        unsigned vb = vb0 + (it % 3) * 9216;

        // S = Q K^T: 16 ldsm4t feed 64 MMAs (2 m-groups each)
        float cs[2][8][4] = {};
        #pragma unroll
        for (int kk = 0; kk < 4; kk++) {
            unsigned ka = kb + ((kk * 16 + l16) * 72) * 2 + joff16;
            #pragma unroll
            for (int jn = 0; jn < 8; jn += 2) {
                unsigned r[4];
                ldsm4t(r, ka + jn * 16);
                #pragma unroll
                for (int mi = 0; mi < 2; mi++) {
                    mma16816(cs[mi][jn],     aq[mi][kk], r[0], r[1]);
                    mma16816(cs[mi][jn + 1], aq[mi][kk], r[2], r[3]);
                }
            }
        }

        // P = 2^S ; rowsum via ones-column HMMA
        unsigned ap[2][4][4];
        #pragma unroll
        for (int mi = 0; mi < 2; mi++) {
            #pragma unroll
            for (int t = 0; t < 4; t++) {
                ap[mi][t][0] = ex2_bf16x2(packu(cs[mi][2 * t][0],     cs[mi][2 * t][1]));
                ap[mi][t][1] = ex2_bf16x2(packu(cs[mi][2 * t][2],     cs[mi][2 * t][3]));
                ap[mi][t][2] = ex2_bf16x2(packu(cs[mi][2 * t + 1][0], cs[mi][2 * t + 1][1]));
                ap[mi][t][3] = ex2_bf16x2(packu(cs[mi][2 * t + 1][2], cs[mi][2 * t + 1][3]));
                mma16816(crow[mi], ap[mi][t], ones_b, ones_b);
            }
        }

        // O += P V: 16 ldsm4 feed 64 MMAs
        #pragma unroll
        for (int t = 0; t < 4; t++) {
            unsigned va = vb + (lr8 * 72 + t * 16 + half8) * 2 + doff;
            #pragma unroll
            for (int dn = 0; dn < 8; dn += 2) {
                unsigned r[4];
                ldsm4(r, va + dn * 8 * 72 * 2);
                #pragma unroll
                for (int mi = 0; mi < 2; mi++) {
                    mma16816(co[mi][dn],     ap[mi][t], r[0], r[1]);
                    mma16816(co[mi][dn + 1], ap[mi][t], r[2], r[3]);
                }
            }
        }
    }

    // write O; torch-faithful reshape: c = nh*64 + (i>>4), p = (i&15)*64 + d
    #pragma unroll
    for (int mi = 0; mi < 2; mi++) {
        float inv0 = 1.f / __shfl_sync(~0u, crow[mi][0], lane & 28);
        float inv1 = 1.f / __shfl_sync(~0u, crow[mi][2], lane & 28);
        int ir0 = i0 + wid * 32 + mi * 16 + (lane >> 2);
        int ir1 = ir0 + 8;
        size_t a0 = ((size_t)(b * C_ + nh * 64 + (ir0 >> 4))) * HW + (ir0 & 15) * 64;
        size_t a1 = ((size_t)(b * C_ + nh * 64 + (ir1 >> 4))) * HW + (ir1 & 15) * 64;
        #pragma unroll
        for (int dn = 0; dn < 8; dn++) {
            int d = dn * 8 + (lane & 3) * 2;
            *(unsigned*)&g_att[a0 + d] = packu(co[mi][dn][0] * inv0, co[mi][dn][1] * inv0);
            *(unsigned*)&g_att[a1 + d] = packu(co[mi][dn][2] * inv1, co[mi][dn][3] * inv1);
        }
    }
}

// ============================ launch ============================
extern "C" void kernel_launch(void* const* d_in, const int* in_sizes, int n_in,
                              void* d_out, int out_size) {
    const float* x      = (const float*)d_in[0];
    const float* gamma  = (const float*)d_in[1];
    const float* beta   = (const float*)d_in[2];
    const float* qkv_w  = (const float*)d_in[3];
    const float* qkv_b  = (const float*)d_in[4];
    const float* proj_w = (const float*)d_in[5];
    const float* proj_b = (const float*)d_in[6];
    float* out = (float*)d_out;

    void *p_h, *p_qkv, *p_att, *p_wq, *p_wp;
    cudaGetSymbolAddress(&p_h, g_h);
    cudaGetSymbolAddress(&p_qkv, g_qkv);
    cudaGetSymbolAddress(&p_att, g_att);
    cudaGetSymbolAddress(&p_wq, g_wq);
    cudaGetSymbolAddress(&p_wp, g_wp);

    const int GEMM_SMEM = 94720;
    const int ATTN_SMEM = 18432 + 2 * 27648;
    const int GN_SMEM   = 65536;
    cudaFuncSetAttribute(gemm_mma<false>,
                         cudaFuncAttributeMaxDynamicSharedMemorySize, GEMM_SMEM);
    cudaFuncSetAttribute(gemm_mma<true>,
                         cudaFuncAttributeMaxDynamicSharedMemorySize, GEMM_SMEM);
    cudaFuncSetAttribute(attn_mma,
                         cudaFuncAttributeMaxDynamicSharedMemorySize, ATTN_SMEM);
    cudaFuncSetAttribute(groupnorm_kernel,
                         cudaFuncAttributeMaxDynamicSharedMemorySize, GN_SMEM);

    wconv2<<<1024, 256>>>(qkv_w, proj_w);

    groupnorm_kernel<<<256, 512, GN_SMEM>>>(x, gamma, beta);

    gemm_mma<false><<<dim3(8, 12, B_), 256, GEMM_SMEM>>>(
        (const bf16*)p_h, (const bf16*)p_wq, qkv_b, nullptr, p_qkv, OC_QKV);

    attn_mma<<<dim3(8, 64), 128, ATTN_SMEM>>>();

    gemm_mma<true><<<dim3(8, 4, B_), 256, GEMM_SMEM>>>(
        (const bf16*)p_att, (const bf16*)p_wp, proj_b, x, out, C_);
}